// round 7
// baseline (speedup 1.0000x reference)
#include <cuda_runtime.h>
#include <cuda_bf16.h>
#include <cuda_fp8.h>
#include <cstdint>
#include <math.h>

// Problem constants
#define B   16
#define L   512
#define D   512
#define NH  8
#define HD  64
#define T   17
#define CYC 2
#define BL  (B * L)   // 8192
#define DD  (D * D)

// ---------------------------------------------------------------------------
// Scratch (device globals)
// ---------------------------------------------------------------------------
__device__ float g_e[BL * D];
__device__ float g_h[BL * D];
__device__ float g_s[B * D];
__device__ float g_qkv[BL * 1536];   // q | k | v
__device__ float g_keve[BL * 1024];  // ke | ve
__device__ float g_krvr[BL * 1024];  // kr | vr
__device__ float g_a[BL * D];
__device__ float g_ks[B * D];
__device__ float g_vs[B * D];
__device__ float g_qsr[B * D];
__device__ float g_ksr[B * D];
__device__ float g_vsr[B * D];
__device__ float g_ctxs[B * D];
__device__ float g_r[B * D];
__device__ float g_bias[8 * D];

// Split activation buffers: bf16 hi + fp8(A) + fp8(256*(A - bf16(A)))
__device__ __align__(16) __nv_bfloat16 g_ehi[BL * D];
__device__ __align__(16) uint8_t       g_eh8[BL * D];
__device__ __align__(16) uint8_t       g_el8[BL * D];
__device__ __align__(16) __nv_bfloat16 g_hhi[BL * D];
__device__ __align__(16) uint8_t       g_hh8[BL * D];
__device__ __align__(16) uint8_t       g_hl8[BL * D];
__device__ __align__(16) __nv_bfloat16 g_cthi[BL * D];
__device__ __align__(16) uint8_t       g_cth8[BL * D];
__device__ __align__(16) uint8_t       g_ctl8[BL * D];
// Weights transposed [N][K]
__device__ __align__(16) __nv_bfloat16 g_whi[8 * DD];
__device__ __align__(16) uint8_t       g_wh8[8 * DD];
__device__ __align__(16) uint8_t       g_wl8[8 * DD];

struct Ptr8 { const float* p[8]; };
struct SJobs { const float* W[3]; const float* bias[3]; float* C[3]; };

__device__ __forceinline__ uint8_t to_fp8(float v) {
    return (uint8_t)__nv_cvt_float_to_fp8(v, __NV_SATFINITE, __NV_E4M3);
}

// ---------------------------------------------------------------------------
// Embedding: e fp32 + splits
// ---------------------------------------------------------------------------
__global__ void embed_split(const int* __restrict__ tokens,
                            const float* __restrict__ emb,
                            float* __restrict__ e,
                            __nv_bfloat16* __restrict__ hi,
                            uint8_t* __restrict__ h8,
                            uint8_t* __restrict__ l8) {
    int idx = blockIdx.x * 256 + threadIdx.x;
    int row = idx / D;
    int d   = idx - row * D;
    float v = emb[tokens[row] * D + d];
    e[idx] = v;
    __nv_bfloat16 hv = __float2bfloat16_rn(v);
    hi[idx] = hv;
    h8[idx] = to_fp8(v);
    l8[idx] = to_fp8((v - __bfloat162float(hv)) * 256.f);
}

// s[b,d] = mean_l e[b,l,d]
__global__ void smean_kernel(const float* __restrict__ e, float* __restrict__ s) {
    __shared__ float red[256];
    int b     = blockIdx.x >> 3;
    int dbase = (blockIdx.x & 7) * 64;
    int tid   = threadIdx.x;
    int d     = dbase + (tid & 63);
    int grp   = tid >> 6;
    const float* p = e + ((b << 9) + grp * 128) * D + d;
    float acc = 0.f;
    #pragma unroll 8
    for (int l = 0; l < 128; l++) acc += p[l * D];
    red[tid] = acc;
    __syncthreads();
    if (tid < 128) red[tid] += red[tid + 128];
    __syncthreads();
    if (tid < 64)
        s[b * D + d] = (red[tid] + red[tid + 64]) * (1.f / (float)L);
}

// ---------------------------------------------------------------------------
// Weight prep: split + transpose; concat biases
// ---------------------------------------------------------------------------
__global__ void wsplit_all(Ptr8 W, __nv_bfloat16* __restrict__ hi,
                           uint8_t* __restrict__ h8, uint8_t* __restrict__ l8) {
    __shared__ float t[32][33];
    const float* Wsrc = W.p[blockIdx.z];
    __nv_bfloat16* hz = hi + blockIdx.z * DD;
    uint8_t* hz8 = h8 + blockIdx.z * DD;
    uint8_t* lz8 = l8 + blockIdx.z * DD;
    int bx = blockIdx.x, by = blockIdx.y;
    int x = threadIdx.x, y = threadIdx.y;
    #pragma unroll
    for (int j = 0; j < 32; j += 8)
        t[y + j][x] = Wsrc[(by * 32 + y + j) * 512 + bx * 32 + x];
    __syncthreads();
    #pragma unroll
    for (int j = 0; j < 32; j += 8) {
        float v = t[x][y + j];
        int n = bx * 32 + y + j;
        int k = by * 32 + x;
        __nv_bfloat16 hv = __float2bfloat16_rn(v);
        hz[n * 512 + k]  = hv;
        hz8[n * 512 + k] = to_fp8(v);
        lz8[n * 512 + k] = to_fp8((v - __bfloat162float(hv)) * 256.f);
    }
}

__global__ void biascat(Ptr8 bsrc, float* __restrict__ dst) {
    int i = blockIdx.x * 256 + threadIdx.x;
    dst[i] = bsrc.p[i >> 9][i & 511];
}

// ---------------------------------------------------------------------------
// Hybrid GEMM: C[8192,N] = A[8192,512] @ Wt[N,512]^T + bias
//   main:  A_hi @ W_hi         (bf16 m16n8k16 HMMA, fp32 accum)
//   corr:  A_hi8@W_lo8 + A_lo8@W_hi8  (e4m3 m16n8k32 QMMA, fp32 accum, /256)
// 128x128 tile, K=32 slabs, 2-stage cp.async (R4 schedule).
// Stage layout, row stride 80B:
//   [0)      A_hi bf16 128x32  (64B/row)
//   [10240)  W_hi bf16 128x32
//   [20480)  A8: per row [A_h8 32B | A_l8 32B | pad 16B]
//   [30720)  W8: per row [W_h8 32B | W_l8 32B | pad 16B]
// ---------------------------------------------------------------------------
#define OFF_WH 10240u
#define OFF_A8 20480u
#define OFF_W8 30720u
#define STG_B  40960u
#define SMEM_G (2 * 40960)   // 81920

__device__ __forceinline__ void mma16816(float* d, const uint32_t* a,
                                         const uint32_t* b) {
    asm volatile("mma.sync.aligned.m16n8k16.row.col.f32.bf16.bf16.f32 "
                 "{%0,%1,%2,%3}, {%4,%5,%6,%7}, {%8,%9}, {%0,%1,%2,%3};"
                 : "+f"(d[0]), "+f"(d[1]), "+f"(d[2]), "+f"(d[3])
                 : "r"(a[0]), "r"(a[1]), "r"(a[2]), "r"(a[3]),
                   "r"(b[0]), "r"(b[1]));
}

__device__ __forceinline__ void qmma(float* d, const uint32_t* a,
                                     const uint32_t* b) {
    asm volatile("mma.sync.aligned.m16n8k32.row.col.f32.e4m3.e4m3.f32 "
                 "{%0,%1,%2,%3}, {%4,%5,%6,%7}, {%8,%9}, {%0,%1,%2,%3};"
                 : "+f"(d[0]), "+f"(d[1]), "+f"(d[2]), "+f"(d[3])
                 : "r"(a[0]), "r"(a[1]), "r"(a[2]), "r"(a[3]),
                   "r"(b[0]), "r"(b[1]));
}

__device__ __forceinline__ void ldsm_x4(uint32_t* r, uint32_t a) {
    asm volatile("ldmatrix.sync.aligned.m8n8.x4.shared.b16 {%0,%1,%2,%3}, [%4];"
                 : "=r"(r[0]), "=r"(r[1]), "=r"(r[2]), "=r"(r[3]) : "r"(a));
}

__global__ void __launch_bounds__(256, 1)
hyb_gemm(const __nv_bfloat16* __restrict__ Ahi, const uint8_t* __restrict__ Ah8,
         const uint8_t* __restrict__ Al8,
         const __nv_bfloat16* __restrict__ Whi, const uint8_t* __restrict__ Wh8,
         const uint8_t* __restrict__ Wl8,
         const float* __restrict__ bias, float* __restrict__ C, int ldc) {
    extern __shared__ __nv_bfloat16 smraw[];
    const int tid  = threadIdx.x;
    const int lane = tid & 31;
    const int warp = tid >> 5;
    const int wm = warp >> 2;        // 0..1
    const int wn = warp & 3;         // 0..3
    const int m0 = blockIdx.y * 128;
    const int n0 = blockIdx.x * 128;

    float accm[4][4][4], accc[4][4][4];
    #pragma unroll
    for (int i = 0; i < 4; i++)
        #pragma unroll
        for (int j = 0; j < 4; j++)
            #pragma unroll
            for (int t = 0; t < 4; t++) { accm[i][j][t] = 0.f; accc[i][j][t] = 0.f; }

    uint32_t smbase = (uint32_t)__cvta_generic_to_shared(smraw);

    auto load_stage = [&](int s, int k0) {
        uint32_t base = smbase + (uint32_t)s * STG_B;
        #pragma unroll
        for (int j = 0; j < 2; j++) {
            int id  = tid + j * 256;
            int row = id >> 2;
            int c   = id & 3;
            // bf16 A / W: 16B chunk at element col c*8
            {
                int ce = c << 3;
                uint32_t dst = base + (uint32_t)(row * 80 + ce * 2);
                asm volatile("cp.async.cg.shared.global [%0], [%1], 16;"
                             :: "r"(dst),
                                "l"(Ahi + (m0 + row) * 512 + k0 + ce));
                asm volatile("cp.async.cg.shared.global [%0], [%1], 16;"
                             :: "r"(dst + OFF_WH),
                                "l"(Whi + (n0 + row) * 512 + k0 + ce));
            }
            // fp8 A8 / W8: chunk c: sel = c>>1 (0=hi,1=lo), cb = (c&1)*16
            {
                int sel = c >> 1;
                int cb  = (c & 1) << 4;
                uint32_t dst = base + (uint32_t)(row * 80 + sel * 32 + cb);
                const uint8_t* sa = (sel ? Al8 : Ah8) + (m0 + row) * 512 + k0 + cb;
                const uint8_t* sw = (sel ? Wl8 : Wh8) + (n0 + row) * 512 + k0 + cb;
                asm volatile("cp.async.cg.shared.global [%0], [%1], 16;"
                             :: "r"(dst + OFF_A8), "l"(sa));
                asm volatile("cp.async.cg.shared.global [%0], [%1], 16;"
                             :: "r"(dst + OFF_W8), "l"(sw));
            }
        }
    };

    load_stage(0, 0);
    asm volatile("cp.async.commit_group;");

    const int lrow  = lane & 15;
    const int lkoff = (lane >> 4) << 3;     // bf16 element col offset (0/8)
    const int lkb8  = (lane >> 4) << 4;     // fp8 byte col offset (0/16)

    #pragma unroll 1
    for (int it = 0; it < 16; it++) {
        if (it < 15) {
            load_stage((it + 1) & 1, (it + 1) * 32);
            asm volatile("cp.async.commit_group;");
            asm volatile("cp.async.wait_group 1;");
        } else {
            asm volatile("cp.async.wait_group 0;");
        }
        __syncthreads();

        uint32_t stg = smbase + (uint32_t)((it & 1)) * STG_B;

        // ---- bf16 main term: two K=16 steps ----
        #pragma unroll
        for (int ks = 0; ks < 2; ks++) {
            int col = ks * 16 + lkoff;
            uint32_t bh[4][2];
            #pragma unroll
            for (int ntp = 0; ntp < 2; ntp++) {
                int n = wn * 32 + ntp * 16 + lrow;
                uint32_t t4[4];
                ldsm_x4(t4, stg + OFF_WH + (uint32_t)(n * 80 + col * 2));
                bh[ntp * 2 + 0][0] = t4[0]; bh[ntp * 2 + 0][1] = t4[2];
                bh[ntp * 2 + 1][0] = t4[1]; bh[ntp * 2 + 1][1] = t4[3];
            }
            #pragma unroll
            for (int mt = 0; mt < 4; mt++) {
                int row = wm * 64 + mt * 16 + lrow;
                uint32_t ah[4];
                ldsm_x4(ah, stg + (uint32_t)(row * 80 + col * 2));
                #pragma unroll
                for (int nt = 0; nt < 4; nt++)
                    mma16816(accm[mt][nt], ah, bh[nt]);
            }
        }

        // ---- fp8 correction terms: one K=32 step ----
        {
            uint32_t bh8[4][2], bl8[4][2];
            #pragma unroll
            for (int ntp = 0; ntp < 2; ntp++) {
                int n = wn * 32 + ntp * 16 + lrow;
                uint32_t t4[4];
                ldsm_x4(t4, stg + OFF_W8 + (uint32_t)(n * 80 + lkb8));
                bh8[ntp * 2 + 0][0] = t4[0]; bh8[ntp * 2 + 0][1] = t4[2];
                bh8[ntp * 2 + 1][0] = t4[1]; bh8[ntp * 2 + 1][1] = t4[3];
                ldsm_x4(t4, stg + OFF_W8 + (uint32_t)(n * 80 + 32 + lkb8));
                bl8[ntp * 2 + 0][0] = t4[0]; bl8[ntp * 2 + 0][1] = t4[2];
                bl8[ntp * 2 + 1][0] = t4[1]; bl8[ntp * 2 + 1][1] = t4[3];
            }
            #pragma unroll
            for (int mt = 0; mt < 4; mt++) {
                int row = wm * 64 + mt * 16 + lrow;
                uint32_t ah8[4], al8[4];
                ldsm_x4(ah8, stg + OFF_A8 + (uint32_t)(row * 80 + lkb8));
                ldsm_x4(al8, stg + OFF_A8 + (uint32_t)(row * 80 + 32 + lkb8));
                #pragma unroll
                for (int nt = 0; nt < 4; nt++) {
                    qmma(accc[mt][nt], ah8, bl8[nt]);   // A_hi @ 256*w_lo
                    qmma(accc[mt][nt], al8, bh8[nt]);   // 256*a_lo @ W_hi
                }
            }
        }
        __syncthreads();
    }

    const int r = lane >> 2;
    const int c = (lane & 3) << 1;
    const float cs = 1.f / 256.f;
    #pragma unroll
    for (int mt = 0; mt < 4; mt++) {
        #pragma unroll
        for (int nt = 0; nt < 4; nt++) {
            int row = m0 + wm * 64 + mt * 16 + r;
            int col = n0 + wn * 32 + nt * 8 + c;
            float b0 = bias[col], b1 = bias[col + 1];
            float2 v0, v1;
            v0.x = accm[mt][nt][0] + accc[mt][nt][0] * cs + b0;
            v0.y = accm[mt][nt][1] + accc[mt][nt][1] * cs + b1;
            v1.x = accm[mt][nt][2] + accc[mt][nt][2] * cs + b0;
            v1.y = accm[mt][nt][3] + accc[mt][nt][3] * cs + b1;
            *(float2*)(C + row * ldc + col)       = v0;
            *(float2*)(C + (row + 8) * ldc + col) = v1;
        }
    }
}

// ---------------------------------------------------------------------------
// Batched small GEMM: C[16,512] = A[16,512] @ W + bias; grid (8, njobs)
// ---------------------------------------------------------------------------
__global__ void __launch_bounds__(256)
sgemm16_multi(const float* __restrict__ A, SJobs jobs) {
    __shared__ float As[16][512];
    int tid = threadIdx.x;
    for (int i = tid; i < 16 * 512; i += 256) As[i >> 9][i & 511] = A[i];
    __syncthreads();
    const float* W  = jobs.W[blockIdx.y];
    const float* bb = jobs.bias[blockIdx.y];
    float*       C  = jobs.C[blockIdx.y];
    int c  = (blockIdx.x << 6) + (tid & 63);
    int rg = (tid >> 6) << 2;
    float a0 = 0.f, a1 = 0.f, a2 = 0.f, a3 = 0.f;
    #pragma unroll 4
    for (int k = 0; k < 512; k++) {
        float w = W[k * 512 + c];
        a0 = fmaf(As[rg + 0][k], w, a0);
        a1 = fmaf(As[rg + 1][k], w, a1);
        a2 = fmaf(As[rg + 2][k], w, a2);
        a3 = fmaf(As[rg + 3][k], w, a3);
    }
    float b = bb[c];
    C[(rg + 0) * 512 + c] = a0 + b;
    C[(rg + 1) * 512 + c] = a1 + b;
    C[(rg + 2) * 512 + c] = a2 + b;
    C[(rg + 3) * 512 + c] = a3 + b;
}

// ---------------------------------------------------------------------------
// sat attention: 5 keys per token; fused split epilogue
// ---------------------------------------------------------------------------
__global__ void sat_attn(const float* __restrict__ QKV, const float* __restrict__ KEVE,
                         const float* __restrict__ Ks,  const float* __restrict__ Vs,
                         __nv_bfloat16* __restrict__ chi, uint8_t* __restrict__ c8,
                         uint8_t* __restrict__ cl8) {
    int t = blockIdx.x;
    int b = t >> 9;
    int l = t & 511;
    int head = threadIdx.x >> 5;
    int lane = threadIdx.x & 31;
    int d0 = head * HD + lane;
    int r0 = (b << 9) + ((l + 1) & 511);
    int r2 = (b << 9) + (l == 0 ? (L - 1) : 0);

    const float* qp = QKV + t * 1536 + d0;
    float q0 = qp[0], q1 = qp[32];
    const float* kp[5] = { QKV + r0 * 1536 + 512 + d0, QKV + t * 1536 + 512 + d0,
                           QKV + r2 * 1536 + 512 + d0, KEVE + t * 1024 + d0,
                           Ks + b * D + d0 };
    const float* vp[5] = { QKV + r0 * 1536 + 1024 + d0, QKV + t * 1536 + 1024 + d0,
                           QKV + r2 * 1536 + 1024 + d0, KEVE + t * 1024 + 512 + d0,
                           Vs + b * D + d0 };
    float sc[5];
    #pragma unroll
    for (int i = 0; i < 5; i++) {
        float p = q0 * kp[i][0] + q1 * kp[i][32];
        #pragma unroll
        for (int o = 16; o > 0; o >>= 1) p += __shfl_xor_sync(0xffffffffu, p, o);
        sc[i] = p * 0.125f;
    }
    float m = sc[0];
    #pragma unroll
    for (int i = 1; i < 5; i++) m = fmaxf(m, sc[i]);
    float den = 0.f;
    #pragma unroll
    for (int i = 0; i < 5; i++) { sc[i] = expf(sc[i] - m); den += sc[i]; }
    float inv = 1.f / den;
    float o0 = 0.f, o1 = 0.f;
    #pragma unroll
    for (int i = 0; i < 5; i++) {
        o0 = fmaf(sc[i], vp[i][0],  o0);
        o1 = fmaf(sc[i], vp[i][32], o1);
    }
    o0 *= inv; o1 *= inv;
    int base = t * D;
    __nv_bfloat16 h0 = __float2bfloat16_rn(o0);
    __nv_bfloat16 h1 = __float2bfloat16_rn(o1);
    chi[base + d0]      = h0;
    chi[base + d0 + 32] = h1;
    c8[base + d0]       = to_fp8(o0);
    c8[base + d0 + 32]  = to_fp8(o1);
    cl8[base + d0]      = to_fp8((o0 - __bfloat162float(h0)) * 256.f);
    cl8[base + d0 + 32] = to_fp8((o1 - __bfloat162float(h1)) * 256.f);
}

// ---------------------------------------------------------------------------
// rel attention: 513 keys
// ---------------------------------------------------------------------------
__global__ void rel_attn(const float* __restrict__ Qs,  const float* __restrict__ Ksr,
                         const float* __restrict__ KrVr, const float* __restrict__ Vsr,
                         float* __restrict__ ctxs) {
    __shared__ float sc[513];
    __shared__ float red[256];
    __shared__ float qsh[HD];
    int b    = blockIdx.x >> 3;
    int head = blockIdx.x & 7;
    int tid  = threadIdx.x;
    int off  = head * HD;

    if (tid < HD) qsh[tid] = Qs[b * D + off + tid];
    __syncthreads();

    for (int k = tid; k < 513; k += 256) {
        const float* kv = (k == 0) ? (Ksr + b * D + off)
                                   : (KrVr + ((b << 9) + k - 1) * 1024 + off);
        float p = 0.f;
        #pragma unroll
        for (int d = 0; d < HD; d++) p = fmaf(qsh[d], kv[d], p);
        sc[k] = p * 0.125f;
    }
    __syncthreads();

    float m = -1e30f;
    for (int k = tid; k < 513; k += 256) m = fmaxf(m, sc[k]);
    red[tid] = m; __syncthreads();
    for (int st = 128; st > 0; st >>= 1) {
        if (tid < st) red[tid] = fmaxf(red[tid], red[tid + st]);
        __syncthreads();
    }
    m = red[0];
    __syncthreads();

    float dsum = 0.f;
    for (int k = tid; k < 513; k += 256) {
        float e_ = expf(sc[k] - m);
        sc[k] = e_;
        dsum += e_;
    }
    red[tid] = dsum; __syncthreads();
    for (int st = 128; st > 0; st >>= 1) {
        if (tid < st) red[tid] += red[tid + st];
        __syncthreads();
    }
    float inv = 1.f / red[0];
    __syncthreads();

    int d = tid & 63;
    int g = tid >> 6;
    float acc = 0.f;
    for (int k = g; k < 513; k += 4) {
        const float* vv = (k == 0) ? (Vsr + b * D + off)
                                   : (KrVr + ((b << 9) + k - 1) * 1024 + 512 + off);
        acc = fmaf(sc[k], vv[d], acc);
    }
    red[tid] = acc;
    __syncthreads();
    if (tid < 64) {
        float o = red[tid] + red[tid + 64] + red[tid + 128] + red[tid + 192];
        ctxs[b * D + off + tid] = o * inv;
    }
}

// ---------------------------------------------------------------------------
// relu + LayerNorm (+ optional split outputs)
// ---------------------------------------------------------------------------
__global__ void relu_ln(const float* __restrict__ x, const float* __restrict__ w,
                        const float* __restrict__ bb, float* __restrict__ out,
                        __nv_bfloat16* __restrict__ hi, uint8_t* __restrict__ h8,
                        uint8_t* __restrict__ l8) {
    __shared__ float red[256];
    int row = blockIdx.x;
    int tid = threadIdx.x;
    float v0 = fmaxf(x[row * D + tid],       0.f);
    float v1 = fmaxf(x[row * D + tid + 256], 0.f);
    red[tid] = v0 + v1;
    __syncthreads();
    for (int st = 128; st > 0; st >>= 1) {
        if (tid < st) red[tid] += red[tid + st];
        __syncthreads();
    }
    float mean = red[0] * (1.f / 512.f);
    __syncthreads();
    float d0 = v0 - mean, d1 = v1 - mean;
    red[tid] = d0 * d0 + d1 * d1;
    __syncthreads();
    for (int st = 128; st > 0; st >>= 1) {
        if (tid < st) red[tid] += red[tid + st];
        __syncthreads();
    }
    float inv = rsqrtf(red[0] * (1.f / 512.f) + 1e-12f);
    float o0 = w[tid]       * d0 * inv + bb[tid];
    float o1 = w[tid + 256] * d1 * inv + bb[tid + 256];
    out[row * D + tid]       = o0;
    out[row * D + tid + 256] = o1;
    if (hi) {
        __nv_bfloat16 h0 = __float2bfloat16_rn(o0);
        __nv_bfloat16 h1 = __float2bfloat16_rn(o1);
        hi[row * D + tid]       = h0;
        hi[row * D + tid + 256] = h1;
        h8[row * D + tid]       = to_fp8(o0);
        h8[row * D + tid + 256] = to_fp8(o1);
        l8[row * D + tid]       = to_fp8((o0 - __bfloat162float(h0)) * 256.f);
        l8[row * D + tid + 256] = to_fp8((o1 - __bfloat162float(h1)) * 256.f);
    }
}

// ---------------------------------------------------------------------------
// logits = h @ ofc_w[512,17] + ofc_b
// ---------------------------------------------------------------------------
__global__ void final_logits(const float* __restrict__ h, const float* __restrict__ W,
                             const float* __restrict__ bias, float* __restrict__ out) {
    __shared__ float Wsh[512 * T];
    int tid = threadIdx.x;
    for (int i = tid; i < 512 * T; i += 256) Wsh[i] = W[i];
    __syncthreads();
    int warp = tid >> 5, lane = tid & 31;
    int row = blockIdx.x * 8 + warp;
    float acc[T];
    #pragma unroll
    for (int t = 0; t < T; t++) acc[t] = 0.f;
    const float* hr = h + row * D;
    for (int k = lane; k < D; k += 32) {
        float a = hr[k];
        #pragma unroll
        for (int t = 0; t < T; t++) acc[t] = fmaf(a, Wsh[k * T + t], acc[t]);
    }
    #pragma unroll
    for (int t = 0; t < T; t++)
        #pragma unroll
        for (int o = 16; o > 0; o >>= 1)
            acc[t] += __shfl_xor_sync(0xffffffffu, acc[t], o);
    if (lane == 0) {
        #pragma unroll
        for (int t = 0; t < T; t++) out[row * T + t] = acc[t] + bias[t];
    }
}

// ---------------------------------------------------------------------------
// Launch
// ---------------------------------------------------------------------------
extern "C" void kernel_launch(void* const* d_in, const int* in_sizes, int n_in,
                              void* d_out, int out_size) {
    (void)in_sizes; (void)n_in; (void)out_size;
    const int*   tokens  = (const int*)  d_in[0];
    const float* emb     = (const float*)d_in[4];
    Ptr8 wsrc = {{ (const float*)d_in[5],  (const float*)d_in[7],
                   (const float*)d_in[9],  (const float*)d_in[11],
                   (const float*)d_in[13], (const float*)d_in[15],
                   (const float*)d_in[17], (const float*)d_in[19] }};
    Ptr8 bsrc = {{ (const float*)d_in[6],  (const float*)d_in[8],
                   (const float*)d_in[10], (const float*)d_in[12],
                   (const float*)d_in[14], (const float*)d_in[16],
                   (const float*)d_in[18], (const float*)d_in[20] }};
    const float* sat_kw = (const float*)d_in[7];
    const float* sat_kb = (const float*)d_in[8];
    const float* sat_vw = (const float*)d_in[9];
    const float* sat_vb = (const float*)d_in[10];
    const float* rel_qw = (const float*)d_in[13];
    const float* rel_qb = (const float*)d_in[14];
    const float* rel_kw = (const float*)d_in[15];
    const float* rel_kb = (const float*)d_in[16];
    const float* rel_vw = (const float*)d_in[17];
    const float* rel_vb = (const float*)d_in[18];
    const float* rel_ow = (const float*)d_in[19];
    const float* rel_ob = (const float*)d_in[20];
    const float* ln_sw  = (const float*)d_in[21];
    const float* ln_sb  = (const float*)d_in[22];
    const float* ln_rw  = (const float*)d_in[23];
    const float* ln_rb  = (const float*)d_in[24];
    const float* ofc_w  = (const float*)d_in[25];
    const float* ofc_b  = (const float*)d_in[26];
    float* out = (float*)d_out;

    float *e, *h, *s, *qkv, *keve, *krvr, *a;
    float *ks, *vs, *qsr, *ksr, *vsr, *ctxs, *r, *bias;
    __nv_bfloat16 *ehi, *hhi, *cthi, *whi;
    uint8_t *eh8, *el8, *hh8, *hl8, *cth8, *ctl8, *wh8, *wl8;
    cudaGetSymbolAddress((void**)&e,    g_e);
    cudaGetSymbolAddress((void**)&h,    g_h);
    cudaGetSymbolAddress((void**)&s,    g_s);
    cudaGetSymbolAddress((void**)&qkv,  g_qkv);
    cudaGetSymbolAddress((void**)&keve, g_keve);
    cudaGetSymbolAddress((void**)&krvr, g_krvr);
    cudaGetSymbolAddress((void**)&a,    g_a);
    cudaGetSymbolAddress((void**)&ks,   g_ks);
    cudaGetSymbolAddress((void**)&vs,   g_vs);
    cudaGetSymbolAddress((void**)&qsr,  g_qsr);
    cudaGetSymbolAddress((void**)&ksr,  g_ksr);
    cudaGetSymbolAddress((void**)&vsr,  g_vsr);
    cudaGetSymbolAddress((void**)&ctxs, g_ctxs);
    cudaGetSymbolAddress((void**)&r,    g_r);
    cudaGetSymbolAddress((void**)&bias, g_bias);
    cudaGetSymbolAddress((void**)&ehi,  g_ehi);
    cudaGetSymbolAddress((void**)&eh8,  g_eh8);
    cudaGetSymbolAddress((void**)&el8,  g_el8);
    cudaGetSymbolAddress((void**)&hhi,  g_hhi);
    cudaGetSymbolAddress((void**)&hh8,  g_hh8);
    cudaGetSymbolAddress((void**)&hl8,  g_hl8);
    cudaGetSymbolAddress((void**)&cthi, g_cthi);
    cudaGetSymbolAddress((void**)&cth8, g_cth8);
    cudaGetSymbolAddress((void**)&ctl8, g_ctl8);
    cudaGetSymbolAddress((void**)&whi,  g_whi);
    cudaGetSymbolAddress((void**)&wh8,  g_wh8);
    cudaGetSymbolAddress((void**)&wl8,  g_wl8);

    cudaFuncSetAttribute(hyb_gemm, cudaFuncAttributeMaxDynamicSharedMemorySize,
                         SMEM_G);

    // Weight prep
    wsplit_all<<<dim3(16, 16, 8), dim3(32, 8)>>>(wsrc, whi, wh8, wl8);
    biascat<<<16, 256>>>(bsrc, bias);

    embed_split<<<BL * D / 256, 256>>>(tokens, emb, e, ehi, eh8, el8);
    smean_kernel<<<B * 8, 256>>>(e, s);

    #define GEMM(AHI, AH8, AL8, WI, NTOT, OUT)                                 \
        hyb_gemm<<<dim3((NTOT) / 128, 64), 256, SMEM_G>>>(                     \
            AHI, AH8, AL8, whi + (WI) * DD, wh8 + (WI) * DD, wl8 + (WI) * DD,  \
            bias + (WI) * 512, OUT, NTOT)

    // e-projections: sat_k | sat_v (weights 1,2 contiguous)
    GEMM(ehi, eh8, el8, 1, 1024, keve);

    for (int c = 0; c < CYC; c++) {
        const __nv_bfloat16* chi_ = c ? hhi : ehi;
        const uint8_t* ch8_ = c ? hh8 : eh8;
        const uint8_t* cl8_ = c ? hl8 : el8;

        {
            SJobs j = {{ sat_kw, sat_vw, nullptr },
                       { sat_kb, sat_vb, nullptr },
                       { ks, vs, nullptr }};
            sgemm16_multi<<<dim3(8, 2), 256>>>(s, j);
        }

        GEMM(chi_, ch8_, cl8_, 0, 1536, qkv);     // q | k | v
        sat_attn<<<BL, 256>>>(qkv, keve, ks, vs, cthi, cth8, ctl8);
        GEMM(cthi, cth8, ctl8, 3, 512, a);        // sat_o
        relu_ln<<<BL, 256>>>(a, ln_sw, ln_sb, h, hhi, hh8, hl8);

        GEMM(hhi, hh8, hl8, 5, 1024, krvr);       // rel_k | rel_v
        {
            SJobs j = {{ rel_qw, rel_kw, rel_vw },
                       { rel_qb, rel_kb, rel_vb },
                       { qsr, ksr, vsr }};
            sgemm16_multi<<<dim3(8, 3), 256>>>(s, j);
        }

        rel_attn<<<B * NH, 256>>>(qsr, ksr, krvr, vsr, ctxs);
        {
            SJobs j = {{ rel_ow, nullptr, nullptr },
                       { rel_ob, nullptr, nullptr },
                       { r, nullptr, nullptr }};
            sgemm16_multi<<<dim3(8, 1), 256>>>(ctxs, j);
        }
        relu_ln<<<B, 256>>>(r, ln_rw, ln_rb, s, nullptr, nullptr, nullptr);
    }

    final_logits<<<BL / 8, 256>>>(h, ofc_w, ofc_b, out);
}

// round 8
// speedup vs baseline: 1.4038x; 1.4038x over previous
#include <cuda_runtime.h>
#include <cuda_bf16.h>
#include <cstdint>
#include <math.h>

// Problem constants
#define B   16
#define L   512
#define D   512
#define NH  8
#define HD  64
#define T   17
#define CYC 2
#define BL  (B * L)   // 8192
#define DD  (D * D)

// ---------------------------------------------------------------------------
// Scratch (device globals)
// ---------------------------------------------------------------------------
__device__ float g_e[BL * D];
__device__ float g_h[BL * D];
__device__ float g_s[B * D];
__device__ float g_qkv[BL * 1536];   // q | k | v
__device__ float g_keve[BL * 1024];  // ke | ve
__device__ float g_krvr[BL * 1024];  // kr | vr
__device__ float g_a[BL * D];
__device__ float g_ks[B * D];
__device__ float g_vs[B * D];
__device__ float g_qsr[B * D];
__device__ float g_ksr[B * D];
__device__ float g_vsr[B * D];
__device__ float g_ctxs[B * D];
__device__ float g_r[B * D];
__device__ float g_bias[8 * D];      // concatenated biases, weight order

// bf16 split buffers (16B aligned for cp.async 16)
__device__ __align__(16) __nv_bfloat16 g_ehi[BL * D];
__device__ __align__(16) __nv_bfloat16 g_elo[BL * D];
__device__ __align__(16) __nv_bfloat16 g_hhi[BL * D];
__device__ __align__(16) __nv_bfloat16 g_hlo[BL * D];
__device__ __align__(16) __nv_bfloat16 g_cthi[BL * D];
__device__ __align__(16) __nv_bfloat16 g_ctlo[BL * D];
__device__ __align__(16) __nv_bfloat16 g_whi[8 * DD];   // transposed [N][K]
__device__ __align__(16) __nv_bfloat16 g_wlo[8 * DD];

struct Ptr8 { const float* p[8]; };
struct SJobs { const float* W[3]; const float* bias[3]; float* C[3]; };

// ---------------------------------------------------------------------------
// Embedding: e fp32 + split bf16
// ---------------------------------------------------------------------------
__global__ void embed_split(const int* __restrict__ tokens,
                            const float* __restrict__ emb,
                            float* __restrict__ e,
                            __nv_bfloat16* __restrict__ hi,
                            __nv_bfloat16* __restrict__ lo) {
    int idx = blockIdx.x * 256 + threadIdx.x;
    int row = idx / D;
    int d   = idx - row * D;
    float v = emb[tokens[row] * D + d];
    e[idx] = v;
    __nv_bfloat16 hv = __float2bfloat16_rn(v);
    hi[idx] = hv;
    lo[idx] = __float2bfloat16_rn(v - __bfloat162float(hv));
}

// s[b,d] = mean_l e[b,l,d] — grid = B*8, block 256 (R5 fast version)
__global__ void smean_kernel(const float* __restrict__ e, float* __restrict__ s) {
    __shared__ float red[256];
    int b     = blockIdx.x >> 3;
    int dbase = (blockIdx.x & 7) * 64;
    int tid   = threadIdx.x;
    int d     = dbase + (tid & 63);
    int grp   = tid >> 6;
    const float* p = e + ((b << 9) + grp * 128) * D + d;
    float acc = 0.f;
    #pragma unroll 8
    for (int l = 0; l < 128; l++) acc += p[l * D];
    red[tid] = acc;
    __syncthreads();
    if (tid < 128) red[tid] += red[tid + 128];
    __syncthreads();
    if (tid < 64)
        s[b * D + d] = (red[tid] + red[tid + 64]) * (1.f / (float)L);
}

// ---------------------------------------------------------------------------
// Weight prep: split + transpose all 8 weights; concat biases
// ---------------------------------------------------------------------------
__global__ void wsplit_all(Ptr8 W, __nv_bfloat16* __restrict__ hi,
                           __nv_bfloat16* __restrict__ lo) {
    __shared__ float t[32][33];
    const float* Wsrc = W.p[blockIdx.z];
    __nv_bfloat16* hz = hi + blockIdx.z * DD;
    __nv_bfloat16* lz = lo + blockIdx.z * DD;
    int bx = blockIdx.x, by = blockIdx.y;
    int x = threadIdx.x, y = threadIdx.y;
    #pragma unroll
    for (int j = 0; j < 32; j += 8)
        t[y + j][x] = Wsrc[(by * 32 + y + j) * 512 + bx * 32 + x];
    __syncthreads();
    #pragma unroll
    for (int j = 0; j < 32; j += 8) {
        float v = t[x][y + j];
        int n = bx * 32 + y + j;
        int k = by * 32 + x;
        __nv_bfloat16 hv = __float2bfloat16_rn(v);
        hz[n * 512 + k] = hv;
        lz[n * 512 + k] = __float2bfloat16_rn(v - __bfloat162float(hv));
    }
}

__global__ void biascat(Ptr8 bsrc, float* __restrict__ dst) {
    int i = blockIdx.x * 256 + threadIdx.x;
    dst[i] = bsrc.p[i >> 9][i & 511];
}

// ---------------------------------------------------------------------------
// Tensor-core GEMM (R4 schedule — known good):
// C[8192,N] = A[8192,512] @ Wt[N,512]^T + bias
// 3-term bf16 split; ldmatrix; 128x128x32 tiles, 2-stage cp.async.
// ---------------------------------------------------------------------------
#define SMEM_STAGE 20480                  // bf16 elems per stage
#define SMEM_BYTES (2 * SMEM_STAGE * 2)   // 81920 B

__device__ __forceinline__ void mma16816(float* d, const uint32_t* a,
                                         const uint32_t* b) {
    asm volatile("mma.sync.aligned.m16n8k16.row.col.f32.bf16.bf16.f32 "
                 "{%0,%1,%2,%3}, {%4,%5,%6,%7}, {%8,%9}, {%0,%1,%2,%3};"
                 : "+f"(d[0]), "+f"(d[1]), "+f"(d[2]), "+f"(d[3])
                 : "r"(a[0]), "r"(a[1]), "r"(a[2]), "r"(a[3]),
                   "r"(b[0]), "r"(b[1]));
}

__device__ __forceinline__ void ldsm_x4(uint32_t* r, uint32_t a) {
    asm volatile("ldmatrix.sync.aligned.m8n8.x4.shared.b16 {%0,%1,%2,%3}, [%4];"
                 : "=r"(r[0]), "=r"(r[1]), "=r"(r[2]), "=r"(r[3]) : "r"(a));
}

__global__ void __launch_bounds__(256, 2)
mma_gemm(const __nv_bfloat16* __restrict__ Ahi, const __nv_bfloat16* __restrict__ Alo,
         const __nv_bfloat16* __restrict__ Whi, const __nv_bfloat16* __restrict__ Wlo,
         const float* __restrict__ bias, float* __restrict__ C, int ldc) {
    extern __shared__ __nv_bfloat16 sm[];
    const int tid  = threadIdx.x;
    const int lane = tid & 31;
    const int warp = tid >> 5;
    const int wm = warp >> 2;        // 0..1
    const int wn = warp & 3;         // 0..3
    const int m0 = blockIdx.y * 128;
    const int n0 = blockIdx.x * 128;

    float acc[4][4][4];
    #pragma unroll
    for (int i = 0; i < 4; i++)
        #pragma unroll
        for (int j = 0; j < 4; j++)
            #pragma unroll
            for (int t = 0; t < 4; t++) acc[i][j][t] = 0.f;

    uint32_t smbase = (uint32_t)__cvta_generic_to_shared(sm);

    auto load_stage = [&](int s, int k0) {
        uint32_t base = smbase + (uint32_t)(s * SMEM_STAGE * 2);
        #pragma unroll
        for (int i = 0; i < 2; i++) {
            int id  = tid + i * 256;
            int row = id >> 2;
            int qc  = (id & 3) << 3;
            uint32_t so = base + (uint32_t)((row * 40 + qc) * 2);
            const __nv_bfloat16* ga = Ahi + (m0 + row) * 512 + k0 + qc;
            const __nv_bfloat16* gb = Alo + (m0 + row) * 512 + k0 + qc;
            const __nv_bfloat16* gc = Whi + (n0 + row) * 512 + k0 + qc;
            const __nv_bfloat16* gd = Wlo + (n0 + row) * 512 + k0 + qc;
            asm volatile("cp.async.cg.shared.global [%0], [%1], 16;" :: "r"(so),           "l"(ga));
            asm volatile("cp.async.cg.shared.global [%0], [%1], 16;" :: "r"(so + 10240u), "l"(gb));
            asm volatile("cp.async.cg.shared.global [%0], [%1], 16;" :: "r"(so + 20480u), "l"(gc));
            asm volatile("cp.async.cg.shared.global [%0], [%1], 16;" :: "r"(so + 30720u), "l"(gd));
        }
    };

    load_stage(0, 0);
    asm volatile("cp.async.commit_group;");

    const int lrow  = lane & 15;
    const int lkoff = (lane >> 4) << 3;

    #pragma unroll 1
    for (int it = 0; it < 16; it++) {
        if (it < 15) {
            load_stage((it + 1) & 1, (it + 1) * 32);
            asm volatile("cp.async.commit_group;");
            asm volatile("cp.async.wait_group 1;");
        } else {
            asm volatile("cp.async.wait_group 0;");
        }
        __syncthreads();

        uint32_t st = smbase + (uint32_t)((it & 1) * SMEM_STAGE * 2);

        #pragma unroll
        for (int ks = 0; ks < 2; ks++) {
            int col = ks * 16 + lkoff;
            uint32_t bh[4][2], bl[4][2];
            #pragma unroll
            for (int ntp = 0; ntp < 2; ntp++) {
                int n = wn * 32 + ntp * 16 + lrow;
                uint32_t adr = st + 20480u + (uint32_t)((n * 40 + col) * 2);
                uint32_t t4[4];
                ldsm_x4(t4, adr);
                bh[ntp * 2 + 0][0] = t4[0]; bh[ntp * 2 + 0][1] = t4[2];
                bh[ntp * 2 + 1][0] = t4[1]; bh[ntp * 2 + 1][1] = t4[3];
                ldsm_x4(t4, adr + 10240u);
                bl[ntp * 2 + 0][0] = t4[0]; bl[ntp * 2 + 0][1] = t4[2];
                bl[ntp * 2 + 1][0] = t4[1]; bl[ntp * 2 + 1][1] = t4[3];
            }
            #pragma unroll
            for (int mt = 0; mt < 4; mt++) {
                int row = wm * 64 + mt * 16 + lrow;
                uint32_t adr = st + (uint32_t)((row * 40 + col) * 2);
                uint32_t ah[4], al[4];
                ldsm_x4(ah, adr);
                ldsm_x4(al, adr + 10240u);
                #pragma unroll
                for (int nt = 0; nt < 4; nt++) {
                    mma16816(acc[mt][nt], ah, bh[nt]);
                    mma16816(acc[mt][nt], ah, bl[nt]);
                    mma16816(acc[mt][nt], al, bh[nt]);
                }
            }
        }
        __syncthreads();
    }

    const int r = lane >> 2;
    const int c = (lane & 3) << 1;
    #pragma unroll
    for (int mt = 0; mt < 4; mt++) {
        #pragma unroll
        for (int nt = 0; nt < 4; nt++) {
            int row = m0 + wm * 64 + mt * 16 + r;
            int col = n0 + wn * 32 + nt * 8 + c;
            float b0 = bias[col], b1 = bias[col + 1];
            float2 v0 = make_float2(acc[mt][nt][0] + b0, acc[mt][nt][1] + b1);
            float2 v1 = make_float2(acc[mt][nt][2] + b0, acc[mt][nt][3] + b1);
            *(float2*)(C + row * ldc + col)       = v0;
            *(float2*)(C + (row + 8) * ldc + col) = v1;
        }
    }
}

// ---------------------------------------------------------------------------
// Batched small GEMM: C[16,512] = A[16,512] @ W + bias; grid (8, njobs)
// ---------------------------------------------------------------------------
__global__ void __launch_bounds__(256)
sgemm16_multi(const float* __restrict__ A, SJobs jobs) {
    __shared__ float As[16][512];
    int tid = threadIdx.x;
    for (int i = tid; i < 16 * 512; i += 256) As[i >> 9][i & 511] = A[i];
    __syncthreads();
    const float* W  = jobs.W[blockIdx.y];
    const float* bb = jobs.bias[blockIdx.y];
    float*       C  = jobs.C[blockIdx.y];
    int c  = (blockIdx.x << 6) + (tid & 63);
    int rg = (tid >> 6) << 2;
    float a0 = 0.f, a1 = 0.f, a2 = 0.f, a3 = 0.f;
    #pragma unroll 4
    for (int k = 0; k < 512; k++) {
        float w = W[k * 512 + c];
        a0 = fmaf(As[rg + 0][k], w, a0);
        a1 = fmaf(As[rg + 1][k], w, a1);
        a2 = fmaf(As[rg + 2][k], w, a2);
        a3 = fmaf(As[rg + 3][k], w, a3);
    }
    float b = bb[c];
    C[(rg + 0) * 512 + c] = a0 + b;
    C[(rg + 1) * 512 + c] = a1 + b;
    C[(rg + 2) * 512 + c] = a2 + b;
    C[(rg + 3) * 512 + c] = a3 + b;
}

// ---------------------------------------------------------------------------
// sat attention: 5 keys per token; fused bf16-split epilogue
// ---------------------------------------------------------------------------
__global__ void sat_attn(const float* __restrict__ QKV, const float* __restrict__ KEVE,
                         const float* __restrict__ Ks,  const float* __restrict__ Vs,
                         __nv_bfloat16* __restrict__ chi, __nv_bfloat16* __restrict__ clo) {
    int t = blockIdx.x;
    int b = t >> 9;
    int l = t & 511;
    int head = threadIdx.x >> 5;
    int lane = threadIdx.x & 31;
    int d0 = head * HD + lane;
    int r0 = (b << 9) + ((l + 1) & 511);
    int r2 = (b << 9) + (l == 0 ? (L - 1) : 0);

    const float* qp = QKV + t * 1536 + d0;
    float q0 = qp[0], q1 = qp[32];
    const float* kp[5] = { QKV + r0 * 1536 + 512 + d0, QKV + t * 1536 + 512 + d0,
                           QKV + r2 * 1536 + 512 + d0, KEVE + t * 1024 + d0,
                           Ks + b * D + d0 };
    const float* vp[5] = { QKV + r0 * 1536 + 1024 + d0, QKV + t * 1536 + 1024 + d0,
                           QKV + r2 * 1536 + 1024 + d0, KEVE + t * 1024 + 512 + d0,
                           Vs + b * D + d0 };
    float sc[5];
    #pragma unroll
    for (int i = 0; i < 5; i++) {
        float p = q0 * kp[i][0] + q1 * kp[i][32];
        #pragma unroll
        for (int o = 16; o > 0; o >>= 1) p += __shfl_xor_sync(0xffffffffu, p, o);
        sc[i] = p * 0.125f;
    }
    float m = sc[0];
    #pragma unroll
    for (int i = 1; i < 5; i++) m = fmaxf(m, sc[i]);
    float den = 0.f;
    #pragma unroll
    for (int i = 0; i < 5; i++) { sc[i] = expf(sc[i] - m); den += sc[i]; }
    float inv = 1.f / den;
    float o0 = 0.f, o1 = 0.f;
    #pragma unroll
    for (int i = 0; i < 5; i++) {
        o0 = fmaf(sc[i], vp[i][0],  o0);
        o1 = fmaf(sc[i], vp[i][32], o1);
    }
    o0 *= inv; o1 *= inv;
    int base = t * D;
    __nv_bfloat16 h0 = __float2bfloat16_rn(o0);
    __nv_bfloat16 h1 = __float2bfloat16_rn(o1);
    chi[base + d0]      = h0;
    chi[base + d0 + 32] = h1;
    clo[base + d0]      = __float2bfloat16_rn(o0 - __bfloat162float(h0));
    clo[base + d0 + 32] = __float2bfloat16_rn(o1 - __bfloat162float(h1));
}

// ---------------------------------------------------------------------------
// rel attention: 513 keys
// ---------------------------------------------------------------------------
__global__ void rel_attn(const float* __restrict__ Qs,  const float* __restrict__ Ksr,
                         const float* __restrict__ KrVr, const float* __restrict__ Vsr,
                         float* __restrict__ ctxs) {
    __shared__ float sc[513];
    __shared__ float red[256];
    __shared__ float qsh[HD];
    int b    = blockIdx.x >> 3;
    int head = blockIdx.x & 7;
    int tid  = threadIdx.x;
    int off  = head * HD;

    if (tid < HD) qsh[tid] = Qs[b * D + off + tid];
    __syncthreads();

    for (int k = tid; k < 513; k += 256) {
        const float* kv = (k == 0) ? (Ksr + b * D + off)
                                   : (KrVr + ((b << 9) + k - 1) * 1024 + off);
        float p = 0.f;
        #pragma unroll
        for (int d = 0; d < HD; d++) p = fmaf(qsh[d], kv[d], p);
        sc[k] = p * 0.125f;
    }
    __syncthreads();

    float m = -1e30f;
    for (int k = tid; k < 513; k += 256) m = fmaxf(m, sc[k]);
    red[tid] = m; __syncthreads();
    for (int st = 128; st > 0; st >>= 1) {
        if (tid < st) red[tid] = fmaxf(red[tid], red[tid + st]);
        __syncthreads();
    }
    m = red[0];
    __syncthreads();

    float dsum = 0.f;
    for (int k = tid; k < 513; k += 256) {
        float e_ = expf(sc[k] - m);
        sc[k] = e_;
        dsum += e_;
    }
    red[tid] = dsum; __syncthreads();
    for (int st = 128; st > 0; st >>= 1) {
        if (tid < st) red[tid] += red[tid + st];
        __syncthreads();
    }
    float inv = 1.f / red[0];
    __syncthreads();

    int d = tid & 63;
    int g = tid >> 6;
    float acc = 0.f;
    for (int k = g; k < 513; k += 4) {
        const float* vv = (k == 0) ? (Vsr + b * D + off)
                                   : (KrVr + ((b << 9) + k - 1) * 1024 + 512 + off);
        acc = fmaf(sc[k], vv[d], acc);
    }
    red[tid] = acc;
    __syncthreads();
    if (tid < 64) {
        float o = red[tid] + red[tid + 64] + red[tid + 128] + red[tid + 192];
        ctxs[b * D + off + tid] = o * inv;
    }
}

// ---------------------------------------------------------------------------
// relu + LayerNorm (+ optional bf16 split outputs)
// ---------------------------------------------------------------------------
__global__ void relu_ln(const float* __restrict__ x, const float* __restrict__ w,
                        const float* __restrict__ bb, float* __restrict__ out,
                        __nv_bfloat16* __restrict__ hi, __nv_bfloat16* __restrict__ lo) {
    __shared__ float red[256];
    int row = blockIdx.x;
    int tid = threadIdx.x;
    float v0 = fmaxf(x[row * D + tid],       0.f);
    float v1 = fmaxf(x[row * D + tid + 256], 0.f);
    red[tid] = v0 + v1;
    __syncthreads();
    for (int st = 128; st > 0; st >>= 1) {
        if (tid < st) red[tid] += red[tid + st];
        __syncthreads();
    }
    float mean = red[0] * (1.f / 512.f);
    __syncthreads();
    float d0 = v0 - mean, d1 = v1 - mean;
    red[tid] = d0 * d0 + d1 * d1;
    __syncthreads();
    for (int st = 128; st > 0; st >>= 1) {
        if (tid < st) red[tid] += red[tid + st];
        __syncthreads();
    }
    float inv = rsqrtf(red[0] * (1.f / 512.f) + 1e-12f);
    float o0 = w[tid]       * d0 * inv + bb[tid];
    float o1 = w[tid + 256] * d1 * inv + bb[tid + 256];
    out[row * D + tid]       = o0;
    out[row * D + tid + 256] = o1;
    if (hi) {
        __nv_bfloat16 h0 = __float2bfloat16_rn(o0);
        __nv_bfloat16 h1 = __float2bfloat16_rn(o1);
        hi[row * D + tid]       = h0;
        hi[row * D + tid + 256] = h1;
        lo[row * D + tid]       = __float2bfloat16_rn(o0 - __bfloat162float(h0));
        lo[row * D + tid + 256] = __float2bfloat16_rn(o1 - __bfloat162float(h1));
    }
}

// ---------------------------------------------------------------------------
// logits = h @ ofc_w[512,17] + ofc_b
// ---------------------------------------------------------------------------
__global__ void final_logits(const float* __restrict__ h, const float* __restrict__ W,
                             const float* __restrict__ bias, float* __restrict__ out) {
    __shared__ float Wsh[512 * T];
    int tid = threadIdx.x;
    for (int i = tid; i < 512 * T; i += 256) Wsh[i] = W[i];
    __syncthreads();
    int warp = tid >> 5, lane = tid & 31;
    int row = blockIdx.x * 8 + warp;
    float acc[T];
    #pragma unroll
    for (int t = 0; t < T; t++) acc[t] = 0.f;
    const float* hr = h + row * D;
    for (int k = lane; k < D; k += 32) {
        float a = hr[k];
        #pragma unroll
        for (int t = 0; t < T; t++) acc[t] = fmaf(a, Wsh[k * T + t], acc[t]);
    }
    #pragma unroll
    for (int t = 0; t < T; t++)
        #pragma unroll
        for (int o = 16; o > 0; o >>= 1)
            acc[t] += __shfl_xor_sync(0xffffffffu, acc[t], o);
    if (lane == 0) {
        #pragma unroll
        for (int t = 0; t < T; t++) out[row * T + t] = acc[t] + bias[t];
    }
}

// ---------------------------------------------------------------------------
// Launch
// ---------------------------------------------------------------------------
extern "C" void kernel_launch(void* const* d_in, const int* in_sizes, int n_in,
                              void* d_out, int out_size) {
    (void)in_sizes; (void)n_in; (void)out_size;
    const int*   tokens  = (const int*)  d_in[0];
    const float* emb     = (const float*)d_in[4];
    Ptr8 wsrc = {{ (const float*)d_in[5],  (const float*)d_in[7],
                   (const float*)d_in[9],  (const float*)d_in[11],
                   (const float*)d_in[13], (const float*)d_in[15],
                   (const float*)d_in[17], (const float*)d_in[19] }};
    Ptr8 bsrc = {{ (const float*)d_in[6],  (const float*)d_in[8],
                   (const float*)d_in[10], (const float*)d_in[12],
                   (const float*)d_in[14], (const float*)d_in[16],
                   (const float*)d_in[18], (const float*)d_in[20] }};
    const float* sat_kw = (const float*)d_in[7];
    const float* sat_kb = (const float*)d_in[8];
    const float* sat_vw = (const float*)d_in[9];
    const float* sat_vb = (const float*)d_in[10];
    const float* rel_qw = (const float*)d_in[13];
    const float* rel_qb = (const float*)d_in[14];
    const float* rel_kw = (const float*)d_in[15];
    const float* rel_kb = (const float*)d_in[16];
    const float* rel_vw = (const float*)d_in[17];
    const float* rel_vb = (const float*)d_in[18];
    const float* rel_ow = (const float*)d_in[19];
    const float* rel_ob = (const float*)d_in[20];
    const float* ln_sw  = (const float*)d_in[21];
    const float* ln_sb  = (const float*)d_in[22];
    const float* ln_rw  = (const float*)d_in[23];
    const float* ln_rb  = (const float*)d_in[24];
    const float* ofc_w  = (const float*)d_in[25];
    const float* ofc_b  = (const float*)d_in[26];
    float* out = (float*)d_out;

    float *e, *h, *s, *qkv, *keve, *krvr, *a;
    float *ks, *vs, *qsr, *ksr, *vsr, *ctxs, *r, *bias;
    __nv_bfloat16 *ehi, *elo, *hhi, *hlo, *cthi, *ctlo, *whi, *wlo;
    cudaGetSymbolAddress((void**)&e,    g_e);
    cudaGetSymbolAddress((void**)&h,    g_h);
    cudaGetSymbolAddress((void**)&s,    g_s);
    cudaGetSymbolAddress((void**)&qkv,  g_qkv);
    cudaGetSymbolAddress((void**)&keve, g_keve);
    cudaGetSymbolAddress((void**)&krvr, g_krvr);
    cudaGetSymbolAddress((void**)&a,    g_a);
    cudaGetSymbolAddress((void**)&ks,   g_ks);
    cudaGetSymbolAddress((void**)&vs,   g_vs);
    cudaGetSymbolAddress((void**)&qsr,  g_qsr);
    cudaGetSymbolAddress((void**)&ksr,  g_ksr);
    cudaGetSymbolAddress((void**)&vsr,  g_vsr);
    cudaGetSymbolAddress((void**)&ctxs, g_ctxs);
    cudaGetSymbolAddress((void**)&r,    g_r);
    cudaGetSymbolAddress((void**)&bias, g_bias);
    cudaGetSymbolAddress((void**)&ehi,  g_ehi);
    cudaGetSymbolAddress((void**)&elo,  g_elo);
    cudaGetSymbolAddress((void**)&hhi,  g_hhi);
    cudaGetSymbolAddress((void**)&hlo,  g_hlo);
    cudaGetSymbolAddress((void**)&cthi, g_cthi);
    cudaGetSymbolAddress((void**)&ctlo, g_ctlo);
    cudaGetSymbolAddress((void**)&whi,  g_whi);
    cudaGetSymbolAddress((void**)&wlo,  g_wlo);

    cudaFuncSetAttribute(mma_gemm, cudaFuncAttributeMaxDynamicSharedMemorySize,
                         SMEM_BYTES);

    // Weight prep
    wsplit_all<<<dim3(16, 16, 8), dim3(32, 8)>>>(wsrc, whi, wlo);
    biascat<<<16, 256>>>(bsrc, bias);

    embed_split<<<BL * D / 256, 256>>>(tokens, emb, e, ehi, elo);
    smean_kernel<<<B * 8, 256>>>(e, s);

    #define GEMM(AHI, ALO, WI, NTOT, OUT)                                      \
        mma_gemm<<<dim3((NTOT) / 128, 64), 256, SMEM_BYTES>>>(                 \
            AHI, ALO, whi + (WI) * DD, wlo + (WI) * DD, bias + (WI) * 512,     \
            OUT, NTOT)

    // e-projections: sat_k | sat_v (weights 1,2 contiguous)
    GEMM(ehi, elo, 1, 1024, keve);

    for (int c = 0; c < CYC; c++) {
        const bool last = (c == CYC - 1);
        const __nv_bfloat16* chi_ = c ? hhi : ehi;
        const __nv_bfloat16* clo_ = c ? hlo : elo;

        {
            SJobs j = {{ sat_kw, sat_vw, nullptr },
                       { sat_kb, sat_vb, nullptr },
                       { ks, vs, nullptr }};
            sgemm16_multi<<<dim3(8, 2), 256>>>(s, j);
        }

        GEMM(chi_, clo_, 0, 1536, qkv);     // q | k | v
        sat_attn<<<BL, 256>>>(qkv, keve, ks, vs, cthi, ctlo);
        GEMM(cthi, ctlo, 3, 512, a);        // sat_o
        // Last cycle: h's bf16 split is dead (no consumer) — skip it.
        relu_ln<<<BL, 256>>>(a, ln_sw, ln_sb, h,
                             last ? nullptr : hhi, last ? nullptr : hlo);

        // The rel path only matters if its output s is consumed by a
        // LATER cycle. On the final cycle it is dead code — skip entirely.
        if (!last) {
            GEMM(hhi, hlo, 5, 1024, krvr);  // rel_k | rel_v
            {
                SJobs j = {{ rel_qw, rel_kw, rel_vw },
                           { rel_qb, rel_kb, rel_vb },
                           { qsr, ksr, vsr }};
                sgemm16_multi<<<dim3(8, 3), 256>>>(s, j);
            }

            rel_attn<<<B * NH, 256>>>(qsr, ksr, krvr, vsr, ctxs);
            {
                SJobs j = {{ rel_ow, nullptr, nullptr },
                           { rel_ob, nullptr, nullptr },
                           { r, nullptr, nullptr }};
                sgemm16_multi<<<dim3(8, 1), 256>>>(ctxs, j);
            }
            relu_ln<<<B, 256>>>(r, ln_rw, ln_rb, s, nullptr, nullptr);
        }
    }

    final_logits<<<BL / 8, 256>>>(h, ofc_w, ofc_b, out);
}

// round 9
// speedup vs baseline: 1.5444x; 1.1002x over previous
#include <cuda_runtime.h>
#include <cuda_bf16.h>
#include <cstdint>
#include <math.h>

// Problem constants
#define B   16
#define L   512
#define D   512
#define NH  8
#define HD  64
#define T   17
#define CYC 2
#define BL  (B * L)   // 8192
#define DD  (D * D)

// ---------------------------------------------------------------------------
// Scratch (device globals)
// ---------------------------------------------------------------------------
__device__ float g_e[BL * D];
__device__ float g_h[BL * D];
__device__ float g_s[B * D];
__device__ float g_qkv[BL * 1536];   // cyc0: q only (ld 512); cyc1: q|k|v (ld 1536)
__device__ float g_keve[BL * 1024];  // ke | ve
__device__ float g_krvr[BL * 1024];  // kr | vr
__device__ float g_a[BL * D];
__device__ float g_ks[B * D];
__device__ float g_vs[B * D];
__device__ float g_qsr[B * D];
__device__ float g_ksr[B * D];
__device__ float g_vsr[B * D];
__device__ float g_ctxs[B * D];
__device__ float g_r[B * D];
__device__ float g_bias[8 * D];      // concatenated biases, weight order

// bf16 split buffers (16B aligned for cp.async 16)
__device__ __align__(16) __nv_bfloat16 g_ehi[BL * D];
__device__ __align__(16) __nv_bfloat16 g_elo[BL * D];
__device__ __align__(16) __nv_bfloat16 g_hhi[BL * D];
__device__ __align__(16) __nv_bfloat16 g_hlo[BL * D];
__device__ __align__(16) __nv_bfloat16 g_cthi[BL * D];
__device__ __align__(16) __nv_bfloat16 g_ctlo[BL * D];
__device__ __align__(16) __nv_bfloat16 g_whi[8 * DD];   // transposed [N][K]
__device__ __align__(16) __nv_bfloat16 g_wlo[8 * DD];

struct Ptr8 { const float* p[8]; };
struct SJobs { const float* W[3]; const float* bias[3]; float* C[3]; };

// ---------------------------------------------------------------------------
// Embedding: e fp32 + split bf16
// ---------------------------------------------------------------------------
__global__ void embed_split(const int* __restrict__ tokens,
                            const float* __restrict__ emb,
                            float* __restrict__ e,
                            __nv_bfloat16* __restrict__ hi,
                            __nv_bfloat16* __restrict__ lo) {
    int idx = blockIdx.x * 256 + threadIdx.x;
    int row = idx / D;
    int d   = idx - row * D;
    float v = emb[tokens[row] * D + d];
    e[idx] = v;
    __nv_bfloat16 hv = __float2bfloat16_rn(v);
    hi[idx] = hv;
    lo[idx] = __float2bfloat16_rn(v - __bfloat162float(hv));
}

// s[b,d] = mean_l e[b,l,d] — grid = B*8, block 256
__global__ void smean_kernel(const float* __restrict__ e, float* __restrict__ s) {
    __shared__ float red[256];
    int b     = blockIdx.x >> 3;
    int dbase = (blockIdx.x & 7) * 64;
    int tid   = threadIdx.x;
    int d     = dbase + (tid & 63);
    int grp   = tid >> 6;
    const float* p = e + ((b << 9) + grp * 128) * D + d;
    float acc = 0.f;
    #pragma unroll 8
    for (int l = 0; l < 128; l++) acc += p[l * D];
    red[tid] = acc;
    __syncthreads();
    if (tid < 128) red[tid] += red[tid + 128];
    __syncthreads();
    if (tid < 64)
        s[b * D + d] = (red[tid] + red[tid + 64]) * (1.f / (float)L);
}

// ---------------------------------------------------------------------------
// Weight prep: split + transpose all 8 weights; concat biases
// ---------------------------------------------------------------------------
__global__ void wsplit_all(Ptr8 W, __nv_bfloat16* __restrict__ hi,
                           __nv_bfloat16* __restrict__ lo) {
    __shared__ float t[32][33];
    const float* Wsrc = W.p[blockIdx.z];
    __nv_bfloat16* hz = hi + blockIdx.z * DD;
    __nv_bfloat16* lz = lo + blockIdx.z * DD;
    int bx = blockIdx.x, by = blockIdx.y;
    int x = threadIdx.x, y = threadIdx.y;
    #pragma unroll
    for (int j = 0; j < 32; j += 8)
        t[y + j][x] = Wsrc[(by * 32 + y + j) * 512 + bx * 32 + x];
    __syncthreads();
    #pragma unroll
    for (int j = 0; j < 32; j += 8) {
        float v = t[x][y + j];
        int n = bx * 32 + y + j;
        int k = by * 32 + x;
        __nv_bfloat16 hv = __float2bfloat16_rn(v);
        hz[n * 512 + k] = hv;
        lz[n * 512 + k] = __float2bfloat16_rn(v - __bfloat162float(hv));
    }
}

__global__ void biascat(Ptr8 bsrc, float* __restrict__ dst) {
    int i = blockIdx.x * 256 + threadIdx.x;
    dst[i] = bsrc.p[i >> 9][i & 511];
}

// ---------------------------------------------------------------------------
// Tensor-core GEMM (R4 schedule — known good):
// C[8192,N] = A[8192,512] @ Wt[N,512]^T + bias
// 3-term bf16 split; ldmatrix; 128x128x32 tiles, 2-stage cp.async.
// ---------------------------------------------------------------------------
#define SMEM_STAGE 20480                  // bf16 elems per stage
#define SMEM_BYTES (2 * SMEM_STAGE * 2)   // 81920 B

__device__ __forceinline__ void mma16816(float* d, const uint32_t* a,
                                         const uint32_t* b) {
    asm volatile("mma.sync.aligned.m16n8k16.row.col.f32.bf16.bf16.f32 "
                 "{%0,%1,%2,%3}, {%4,%5,%6,%7}, {%8,%9}, {%0,%1,%2,%3};"
                 : "+f"(d[0]), "+f"(d[1]), "+f"(d[2]), "+f"(d[3])
                 : "r"(a[0]), "r"(a[1]), "r"(a[2]), "r"(a[3]),
                   "r"(b[0]), "r"(b[1]));
}

__device__ __forceinline__ void ldsm_x4(uint32_t* r, uint32_t a) {
    asm volatile("ldmatrix.sync.aligned.m8n8.x4.shared.b16 {%0,%1,%2,%3}, [%4];"
                 : "=r"(r[0]), "=r"(r[1]), "=r"(r[2]), "=r"(r[3]) : "r"(a));
}

__global__ void __launch_bounds__(256, 2)
mma_gemm(const __nv_bfloat16* __restrict__ Ahi, const __nv_bfloat16* __restrict__ Alo,
         const __nv_bfloat16* __restrict__ Whi, const __nv_bfloat16* __restrict__ Wlo,
         const float* __restrict__ bias, float* __restrict__ C, int ldc) {
    extern __shared__ __nv_bfloat16 sm[];
    const int tid  = threadIdx.x;
    const int lane = tid & 31;
    const int warp = tid >> 5;
    const int wm = warp >> 2;        // 0..1
    const int wn = warp & 3;         // 0..3
    const int m0 = blockIdx.y * 128;
    const int n0 = blockIdx.x * 128;

    float acc[4][4][4];
    #pragma unroll
    for (int i = 0; i < 4; i++)
        #pragma unroll
        for (int j = 0; j < 4; j++)
            #pragma unroll
            for (int t = 0; t < 4; t++) acc[i][j][t] = 0.f;

    uint32_t smbase = (uint32_t)__cvta_generic_to_shared(sm);

    auto load_stage = [&](int s, int k0) {
        uint32_t base = smbase + (uint32_t)(s * SMEM_STAGE * 2);
        #pragma unroll
        for (int i = 0; i < 2; i++) {
            int id  = tid + i * 256;
            int row = id >> 2;
            int qc  = (id & 3) << 3;
            uint32_t so = base + (uint32_t)((row * 40 + qc) * 2);
            const __nv_bfloat16* ga = Ahi + (m0 + row) * 512 + k0 + qc;
            const __nv_bfloat16* gb = Alo + (m0 + row) * 512 + k0 + qc;
            const __nv_bfloat16* gc = Whi + (n0 + row) * 512 + k0 + qc;
            const __nv_bfloat16* gd = Wlo + (n0 + row) * 512 + k0 + qc;
            asm volatile("cp.async.cg.shared.global [%0], [%1], 16;" :: "r"(so),           "l"(ga));
            asm volatile("cp.async.cg.shared.global [%0], [%1], 16;" :: "r"(so + 10240u), "l"(gb));
            asm volatile("cp.async.cg.shared.global [%0], [%1], 16;" :: "r"(so + 20480u), "l"(gc));
            asm volatile("cp.async.cg.shared.global [%0], [%1], 16;" :: "r"(so + 30720u), "l"(gd));
        }
    };

    load_stage(0, 0);
    asm volatile("cp.async.commit_group;");

    const int lrow  = lane & 15;
    const int lkoff = (lane >> 4) << 3;

    #pragma unroll 1
    for (int it = 0; it < 16; it++) {
        if (it < 15) {
            load_stage((it + 1) & 1, (it + 1) * 32);
            asm volatile("cp.async.commit_group;");
            asm volatile("cp.async.wait_group 1;");
        } else {
            asm volatile("cp.async.wait_group 0;");
        }
        __syncthreads();

        uint32_t st = smbase + (uint32_t)((it & 1) * SMEM_STAGE * 2);

        #pragma unroll
        for (int ks = 0; ks < 2; ks++) {
            int col = ks * 16 + lkoff;
            uint32_t bh[4][2], bl[4][2];
            #pragma unroll
            for (int ntp = 0; ntp < 2; ntp++) {
                int n = wn * 32 + ntp * 16 + lrow;
                uint32_t adr = st + 20480u + (uint32_t)((n * 40 + col) * 2);
                uint32_t t4[4];
                ldsm_x4(t4, adr);
                bh[ntp * 2 + 0][0] = t4[0]; bh[ntp * 2 + 0][1] = t4[2];
                bh[ntp * 2 + 1][0] = t4[1]; bh[ntp * 2 + 1][1] = t4[3];
                ldsm_x4(t4, adr + 10240u);
                bl[ntp * 2 + 0][0] = t4[0]; bl[ntp * 2 + 0][1] = t4[2];
                bl[ntp * 2 + 1][0] = t4[1]; bl[ntp * 2 + 1][1] = t4[3];
            }
            #pragma unroll
            for (int mt = 0; mt < 4; mt++) {
                int row = wm * 64 + mt * 16 + lrow;
                uint32_t adr = st + (uint32_t)((row * 40 + col) * 2);
                uint32_t ah[4], al[4];
                ldsm_x4(ah, adr);
                ldsm_x4(al, adr + 10240u);
                #pragma unroll
                for (int nt = 0; nt < 4; nt++) {
                    mma16816(acc[mt][nt], ah, bh[nt]);
                    mma16816(acc[mt][nt], ah, bl[nt]);
                    mma16816(acc[mt][nt], al, bh[nt]);
                }
            }
        }
        __syncthreads();
    }

    const int r = lane >> 2;
    const int c = (lane & 3) << 1;
    #pragma unroll
    for (int mt = 0; mt < 4; mt++) {
        #pragma unroll
        for (int nt = 0; nt < 4; nt++) {
            int row = m0 + wm * 64 + mt * 16 + r;
            int col = n0 + wn * 32 + nt * 8 + c;
            float b0 = bias[col], b1 = bias[col + 1];
            float2 v0 = make_float2(acc[mt][nt][0] + b0, acc[mt][nt][1] + b1);
            float2 v1 = make_float2(acc[mt][nt][2] + b0, acc[mt][nt][3] + b1);
            *(float2*)(C + row * ldc + col)       = v0;
            *(float2*)(C + (row + 8) * ldc + col) = v1;
        }
    }
}

// ---------------------------------------------------------------------------
// Batched small GEMM: C[16,512] = A[16,512] @ W + bias; grid (8, njobs)
// ---------------------------------------------------------------------------
__global__ void __launch_bounds__(256)
sgemm16_multi(const float* __restrict__ A, SJobs jobs) {
    __shared__ float As[16][512];
    int tid = threadIdx.x;
    for (int i = tid; i < 16 * 512; i += 256) As[i >> 9][i & 511] = A[i];
    __syncthreads();
    const float* W  = jobs.W[blockIdx.y];
    const float* bb = jobs.bias[blockIdx.y];
    float*       C  = jobs.C[blockIdx.y];
    int c  = (blockIdx.x << 6) + (tid & 63);
    int rg = (tid >> 6) << 2;
    float a0 = 0.f, a1 = 0.f, a2 = 0.f, a3 = 0.f;
    #pragma unroll 4
    for (int k = 0; k < 512; k++) {
        float w = W[k * 512 + c];
        a0 = fmaf(As[rg + 0][k], w, a0);
        a1 = fmaf(As[rg + 1][k], w, a1);
        a2 = fmaf(As[rg + 2][k], w, a2);
        a3 = fmaf(As[rg + 3][k], w, a3);
    }
    float b = bb[c];
    C[(rg + 0) * 512 + c] = a0 + b;
    C[(rg + 1) * 512 + c] = a1 + b;
    C[(rg + 2) * 512 + c] = a2 + b;
    C[(rg + 3) * 512 + c] = a3 + b;
}

// ---------------------------------------------------------------------------
// sat attention: 5 keys per token; generalized source pointers/strides
// (cycle 0: K(h)=K(e), V(h)=V(e) — everything reads from keve)
// ---------------------------------------------------------------------------
__global__ void sat_attn(const float* __restrict__ Q,  int ldq,
                         const float* __restrict__ Kh, const float* __restrict__ Vh,
                         int ldkv,
                         const float* __restrict__ Ke, const float* __restrict__ Ve,
                         int ldke,
                         const float* __restrict__ Ks,  const float* __restrict__ Vs,
                         __nv_bfloat16* __restrict__ chi, __nv_bfloat16* __restrict__ clo) {
    int t = blockIdx.x;
    int b = t >> 9;
    int l = t & 511;
    int head = threadIdx.x >> 5;
    int lane = threadIdx.x & 31;
    int d0 = head * HD + lane;
    int r0 = (b << 9) + ((l + 1) & 511);
    int r2 = (b << 9) + (l == 0 ? (L - 1) : 0);

    const float* qp = Q + (size_t)t * ldq + d0;
    float q0 = qp[0], q1 = qp[32];
    const float* kp[5] = { Kh + (size_t)r0 * ldkv + d0, Kh + (size_t)t * ldkv + d0,
                           Kh + (size_t)r2 * ldkv + d0, Ke + (size_t)t * ldke + d0,
                           Ks + b * D + d0 };
    const float* vp[5] = { Vh + (size_t)r0 * ldkv + d0, Vh + (size_t)t * ldkv + d0,
                           Vh + (size_t)r2 * ldkv + d0, Ve + (size_t)t * ldke + d0,
                           Vs + b * D + d0 };
    float sc[5];
    #pragma unroll
    for (int i = 0; i < 5; i++) {
        float p = q0 * kp[i][0] + q1 * kp[i][32];
        #pragma unroll
        for (int o = 16; o > 0; o >>= 1) p += __shfl_xor_sync(0xffffffffu, p, o);
        sc[i] = p * 0.125f;
    }
    float m = sc[0];
    #pragma unroll
    for (int i = 1; i < 5; i++) m = fmaxf(m, sc[i]);
    float den = 0.f;
    #pragma unroll
    for (int i = 0; i < 5; i++) { sc[i] = expf(sc[i] - m); den += sc[i]; }
    float inv = 1.f / den;
    float o0 = 0.f, o1 = 0.f;
    #pragma unroll
    for (int i = 0; i < 5; i++) {
        o0 = fmaf(sc[i], vp[i][0],  o0);
        o1 = fmaf(sc[i], vp[i][32], o1);
    }
    o0 *= inv; o1 *= inv;
    int base = t * D;
    __nv_bfloat16 h0 = __float2bfloat16_rn(o0);
    __nv_bfloat16 h1 = __float2bfloat16_rn(o1);
    chi[base + d0]      = h0;
    chi[base + d0 + 32] = h1;
    clo[base + d0]      = __float2bfloat16_rn(o0 - __bfloat162float(h0));
    clo[base + d0 + 32] = __float2bfloat16_rn(o1 - __bfloat162float(h1));
}

// ---------------------------------------------------------------------------
// rel attention: 513 keys
// ---------------------------------------------------------------------------
__global__ void rel_attn(const float* __restrict__ Qs,  const float* __restrict__ Ksr,
                         const float* __restrict__ KrVr, const float* __restrict__ Vsr,
                         float* __restrict__ ctxs) {
    __shared__ float sc[513];
    __shared__ float red[256];
    __shared__ float qsh[HD];
    int b    = blockIdx.x >> 3;
    int head = blockIdx.x & 7;
    int tid  = threadIdx.x;
    int off  = head * HD;

    if (tid < HD) qsh[tid] = Qs[b * D + off + tid];
    __syncthreads();

    for (int k = tid; k < 513; k += 256) {
        const float* kv = (k == 0) ? (Ksr + b * D + off)
                                   : (KrVr + ((b << 9) + k - 1) * 1024 + off);
        float p = 0.f;
        #pragma unroll
        for (int d = 0; d < HD; d++) p = fmaf(qsh[d], kv[d], p);
        sc[k] = p * 0.125f;
    }
    __syncthreads();

    float m = -1e30f;
    for (int k = tid; k < 513; k += 256) m = fmaxf(m, sc[k]);
    red[tid] = m; __syncthreads();
    for (int st = 128; st > 0; st >>= 1) {
        if (tid < st) red[tid] = fmaxf(red[tid], red[tid + st]);
        __syncthreads();
    }
    m = red[0];
    __syncthreads();

    float dsum = 0.f;
    for (int k = tid; k < 513; k += 256) {
        float e_ = expf(sc[k] - m);
        sc[k] = e_;
        dsum += e_;
    }
    red[tid] = dsum; __syncthreads();
    for (int st = 128; st > 0; st >>= 1) {
        if (tid < st) red[tid] += red[tid + st];
        __syncthreads();
    }
    float inv = 1.f / red[0];
    __syncthreads();

    int d = tid & 63;
    int g = tid >> 6;
    float acc = 0.f;
    for (int k = g; k < 513; k += 4) {
        const float* vv = (k == 0) ? (Vsr + b * D + off)
                                   : (KrVr + ((b << 9) + k - 1) * 1024 + 512 + off);
        acc = fmaf(sc[k], vv[d], acc);
    }
    red[tid] = acc;
    __syncthreads();
    if (tid < 64) {
        float o = red[tid] + red[tid + 64] + red[tid + 128] + red[tid + 192];
        ctxs[b * D + off + tid] = o * inv;
    }
}

// ---------------------------------------------------------------------------
// relu + LayerNorm (+ optional bf16 split outputs)
// ---------------------------------------------------------------------------
__global__ void relu_ln(const float* __restrict__ x, const float* __restrict__ w,
                        const float* __restrict__ bb, float* __restrict__ out,
                        __nv_bfloat16* __restrict__ hi, __nv_bfloat16* __restrict__ lo) {
    __shared__ float red[256];
    int row = blockIdx.x;
    int tid = threadIdx.x;
    float v0 = fmaxf(x[row * D + tid],       0.f);
    float v1 = fmaxf(x[row * D + tid + 256], 0.f);
    red[tid] = v0 + v1;
    __syncthreads();
    for (int st = 128; st > 0; st >>= 1) {
        if (tid < st) red[tid] += red[tid + st];
        __syncthreads();
    }
    float mean = red[0] * (1.f / 512.f);
    __syncthreads();
    float d0 = v0 - mean, d1 = v1 - mean;
    red[tid] = d0 * d0 + d1 * d1;
    __syncthreads();
    for (int st = 128; st > 0; st >>= 1) {
        if (tid < st) red[tid] += red[tid + st];
        __syncthreads();
    }
    float inv = rsqrtf(red[0] * (1.f / 512.f) + 1e-12f);
    float o0 = w[tid]       * d0 * inv + bb[tid];
    float o1 = w[tid + 256] * d1 * inv + bb[tid + 256];
    out[row * D + tid]       = o0;
    out[row * D + tid + 256] = o1;
    if (hi) {
        __nv_bfloat16 h0 = __float2bfloat16_rn(o0);
        __nv_bfloat16 h1 = __float2bfloat16_rn(o1);
        hi[row * D + tid]       = h0;
        hi[row * D + tid + 256] = h1;
        lo[row * D + tid]       = __float2bfloat16_rn(o0 - __bfloat162float(h0));
        lo[row * D + tid + 256] = __float2bfloat16_rn(o1 - __bfloat162float(h1));
    }
}

// ---------------------------------------------------------------------------
// logits = h @ ofc_w[512,17] + ofc_b
// ---------------------------------------------------------------------------
__global__ void final_logits(const float* __restrict__ h, const float* __restrict__ W,
                             const float* __restrict__ bias, float* __restrict__ out) {
    __shared__ float Wsh[512 * T];
    int tid = threadIdx.x;
    for (int i = tid; i < 512 * T; i += 256) Wsh[i] = W[i];
    __syncthreads();
    int warp = tid >> 5, lane = tid & 31;
    int row = blockIdx.x * 8 + warp;
    float acc[T];
    #pragma unroll
    for (int t = 0; t < T; t++) acc[t] = 0.f;
    const float* hr = h + row * D;
    for (int k = lane; k < D; k += 32) {
        float a = hr[k];
        #pragma unroll
        for (int t = 0; t < T; t++) acc[t] = fmaf(a, Wsh[k * T + t], acc[t]);
    }
    #pragma unroll
    for (int t = 0; t < T; t++)
        #pragma unroll
        for (int o = 16; o > 0; o >>= 1)
            acc[t] += __shfl_xor_sync(0xffffffffu, acc[t], o);
    if (lane == 0) {
        #pragma unroll
        for (int t = 0; t < T; t++) out[row * T + t] = acc[t] + bias[t];
    }
}

// ---------------------------------------------------------------------------
// Launch
// ---------------------------------------------------------------------------
extern "C" void kernel_launch(void* const* d_in, const int* in_sizes, int n_in,
                              void* d_out, int out_size) {
    (void)in_sizes; (void)n_in; (void)out_size;
    const int*   tokens  = (const int*)  d_in[0];
    const float* emb     = (const float*)d_in[4];
    Ptr8 wsrc = {{ (const float*)d_in[5],  (const float*)d_in[7],
                   (const float*)d_in[9],  (const float*)d_in[11],
                   (const float*)d_in[13], (const float*)d_in[15],
                   (const float*)d_in[17], (const float*)d_in[19] }};
    Ptr8 bsrc = {{ (const float*)d_in[6],  (const float*)d_in[8],
                   (const float*)d_in[10], (const float*)d_in[12],
                   (const float*)d_in[14], (const float*)d_in[16],
                   (const float*)d_in[18], (const float*)d_in[20] }};
    const float* sat_kw = (const float*)d_in[7];
    const float* sat_kb = (const float*)d_in[8];
    const float* sat_vw = (const float*)d_in[9];
    const float* sat_vb = (const float*)d_in[10];
    const float* rel_qw = (const float*)d_in[13];
    const float* rel_qb = (const float*)d_in[14];
    const float* rel_kw = (const float*)d_in[15];
    const float* rel_kb = (const float*)d_in[16];
    const float* rel_vw = (const float*)d_in[17];
    const float* rel_vb = (const float*)d_in[18];
    const float* rel_ow = (const float*)d_in[19];
    const float* rel_ob = (const float*)d_in[20];
    const float* ln_sw  = (const float*)d_in[21];
    const float* ln_sb  = (const float*)d_in[22];
    const float* ln_rw  = (const float*)d_in[23];
    const float* ln_rb  = (const float*)d_in[24];
    const float* ofc_w  = (const float*)d_in[25];
    const float* ofc_b  = (const float*)d_in[26];
    float* out = (float*)d_out;

    float *e, *h, *s, *qkv, *keve, *krvr, *a;
    float *ks, *vs, *qsr, *ksr, *vsr, *ctxs, *r, *bias;
    __nv_bfloat16 *ehi, *elo, *hhi, *hlo, *cthi, *ctlo, *whi, *wlo;
    cudaGetSymbolAddress((void**)&e,    g_e);
    cudaGetSymbolAddress((void**)&h,    g_h);
    cudaGetSymbolAddress((void**)&s,    g_s);
    cudaGetSymbolAddress((void**)&qkv,  g_qkv);
    cudaGetSymbolAddress((void**)&keve, g_keve);
    cudaGetSymbolAddress((void**)&krvr, g_krvr);
    cudaGetSymbolAddress((void**)&a,    g_a);
    cudaGetSymbolAddress((void**)&ks,   g_ks);
    cudaGetSymbolAddress((void**)&vs,   g_vs);
    cudaGetSymbolAddress((void**)&qsr,  g_qsr);
    cudaGetSymbolAddress((void**)&ksr,  g_ksr);
    cudaGetSymbolAddress((void**)&vsr,  g_vsr);
    cudaGetSymbolAddress((void**)&ctxs, g_ctxs);
    cudaGetSymbolAddress((void**)&r,    g_r);
    cudaGetSymbolAddress((void**)&bias, g_bias);
    cudaGetSymbolAddress((void**)&ehi,  g_ehi);
    cudaGetSymbolAddress((void**)&elo,  g_elo);
    cudaGetSymbolAddress((void**)&hhi,  g_hhi);
    cudaGetSymbolAddress((void**)&hlo,  g_hlo);
    cudaGetSymbolAddress((void**)&cthi, g_cthi);
    cudaGetSymbolAddress((void**)&ctlo, g_ctlo);
    cudaGetSymbolAddress((void**)&whi,  g_whi);
    cudaGetSymbolAddress((void**)&wlo,  g_wlo);

    cudaFuncSetAttribute(mma_gemm, cudaFuncAttributeMaxDynamicSharedMemorySize,
                         SMEM_BYTES);

    #define GEMM(AHI, ALO, WI, NTOT, OUT, LDC)                                 \
        mma_gemm<<<dim3((NTOT) / 128, 64), 256, SMEM_BYTES>>>(                 \
            AHI, ALO, whi + (WI) * DD, wlo + (WI) * DD, bias + (WI) * 512,     \
            OUT, LDC)

    // Weight prep
    wsplit_all<<<dim3(16, 16, 8), dim3(32, 8)>>>(wsrc, whi, wlo);
    biascat<<<16, 256>>>(bsrc, bias);

    embed_split<<<BL * D / 256, 256>>>(tokens, emb, e, ehi, elo);

    // e-projections: sat_k | sat_v (weights 1,2 contiguous).
    // Placed BEFORE smean so ncu's fixed capture slot lands on mma_gemm.
    GEMM(ehi, elo, 1, 1024, keve, 1024);

    smean_kernel<<<B * 8, 256>>>(e, s);

    for (int c = 0; c < CYC; c++) {
        const bool last = (c == CYC - 1);

        {
            SJobs j = {{ sat_kw, sat_vw, nullptr },
                       { sat_kb, sat_vb, nullptr },
                       { ks, vs, nullptr }};
            sgemm16_multi<<<dim3(8, 2), 256>>>(s, j);
        }

        if (c == 0) {
            // h == e: K(h), V(h) identical to keve — only q is new.
            GEMM(ehi, elo, 0, 512, qkv, 512);
            sat_attn<<<BL, 256>>>(qkv, 512,
                                  keve, keve + 512, 1024,
                                  keve, keve + 512, 1024,
                                  ks, vs, cthi, ctlo);
        } else {
            GEMM(hhi, hlo, 0, 1536, qkv, 1536);   // q | k | v
            sat_attn<<<BL, 256>>>(qkv, 1536,
                                  qkv + 512, qkv + 1024, 1536,
                                  keve, keve + 512, 1024,
                                  ks, vs, cthi, ctlo);
        }

        GEMM(cthi, ctlo, 3, 512, a, 512);         // sat_o
        relu_ln<<<BL, 256>>>(a, ln_sw, ln_sb, h,
                             last ? nullptr : hhi, last ? nullptr : hlo);

        // rel path is dead on the final cycle (s never consumed again)
        if (!last) {
            GEMM(hhi, hlo, 5, 1024, krvr, 1024);  // rel_k | rel_v
            {
                SJobs j = {{ rel_qw, rel_kw, rel_vw },
                           { rel_qb, rel_kb, rel_vb },
                           { qsr, ksr, vsr }};
                sgemm16_multi<<<dim3(8, 3), 256>>>(s, j);
            }

            rel_attn<<<B * NH, 256>>>(qsr, ksr, krvr, vsr, ctxs);
            {
                SJobs j = {{ rel_ow, nullptr, nullptr },
                           { rel_ob, nullptr, nullptr },
                           { r, nullptr, nullptr }};
                sgemm16_multi<<<dim3(8, 1), 256>>>(ctxs, j);
            }
            relu_ln<<<B, 256>>>(r, ln_rw, ln_rb, s, nullptr, nullptr);
        }
    }

    final_logits<<<BL / 8, 256>>>(h, ofc_w, ofc_b, out);
}

// round 10
// speedup vs baseline: 2.0096x; 1.3012x over previous
#include <cuda_runtime.h>
#include <cuda_bf16.h>
#include <cstdint>
#include <math.h>

// Problem constants
#define B   16
#define L   512
#define D   512
#define NH  8
#define HD  64
#define T   17
#define CYC 2
#define BL  (B * L)   // 8192
#define DD  (D * D)

// ---------------------------------------------------------------------------
// Scratch (device globals)
// ---------------------------------------------------------------------------
__device__ float g_e[BL * D];
__device__ float g_h[BL * D];
__device__ float g_s[B * D];
__device__ float g_qkv[BL * 1536];   // cyc0: q only (ld 512); cyc1: q|k|v (ld 1536)
__device__ float g_keve[BL * 1024];  // ke | ve
__device__ float g_krvr[BL * 1024];  // kr | vr
__device__ float g_a[BL * D];
__device__ float g_ks[B * D];
__device__ float g_vs[B * D];
__device__ float g_qsr[B * D];
__device__ float g_ksr[B * D];
__device__ float g_vsr[B * D];
__device__ float g_ctxs[B * D];
__device__ float g_r[B * D];
__device__ float g_bias[8 * D];      // concatenated biases, weight order
__device__ float g_part[3 * 8 * 16 * 512];   // small-gemm K-split partials

// bf16 split buffers (16B aligned for cp.async 16)
__device__ __align__(16) __nv_bfloat16 g_ehi[BL * D];
__device__ __align__(16) __nv_bfloat16 g_elo[BL * D];
__device__ __align__(16) __nv_bfloat16 g_hhi[BL * D];
__device__ __align__(16) __nv_bfloat16 g_hlo[BL * D];
__device__ __align__(16) __nv_bfloat16 g_cthi[BL * D];
__device__ __align__(16) __nv_bfloat16 g_ctlo[BL * D];
__device__ __align__(16) __nv_bfloat16 g_whi[8 * DD];   // transposed [N][K]
__device__ __align__(16) __nv_bfloat16 g_wlo[8 * DD];

struct Ptr8 { const float* p[8]; };
struct SJobs { const float* W[3]; const float* bias[3]; float* C[3]; };

// ---------------------------------------------------------------------------
// Embedding: e fp32 + split bf16
// ---------------------------------------------------------------------------
__global__ void embed_split(const int* __restrict__ tokens,
                            const float* __restrict__ emb,
                            float* __restrict__ e,
                            __nv_bfloat16* __restrict__ hi,
                            __nv_bfloat16* __restrict__ lo) {
    int idx = blockIdx.x * 256 + threadIdx.x;
    int row = idx / D;
    int d   = idx - row * D;
    float v = emb[tokens[row] * D + d];
    e[idx] = v;
    __nv_bfloat16 hv = __float2bfloat16_rn(v);
    hi[idx] = hv;
    lo[idx] = __float2bfloat16_rn(v - __bfloat162float(hv));
}

// s[b,d] = mean_l e[b,l,d] — grid = B*8, block 256
__global__ void smean_kernel(const float* __restrict__ e, float* __restrict__ s) {
    __shared__ float red[256];
    int b     = blockIdx.x >> 3;
    int dbase = (blockIdx.x & 7) * 64;
    int tid   = threadIdx.x;
    int d     = dbase + (tid & 63);
    int grp   = tid >> 6;
    const float* p = e + ((b << 9) + grp * 128) * D + d;
    float acc = 0.f;
    #pragma unroll 8
    for (int l = 0; l < 128; l++) acc += p[l * D];
    red[tid] = acc;
    __syncthreads();
    if (tid < 128) red[tid] += red[tid + 128];
    __syncthreads();
    if (tid < 64)
        s[b * D + d] = (red[tid] + red[tid + 64]) * (1.f / (float)L);
}

// ---------------------------------------------------------------------------
// Weight prep: split + transpose all 8 weights; concat biases
// ---------------------------------------------------------------------------
__global__ void wsplit_all(Ptr8 W, __nv_bfloat16* __restrict__ hi,
                           __nv_bfloat16* __restrict__ lo) {
    __shared__ float t[32][33];
    const float* Wsrc = W.p[blockIdx.z];
    __nv_bfloat16* hz = hi + blockIdx.z * DD;
    __nv_bfloat16* lz = lo + blockIdx.z * DD;
    int bx = blockIdx.x, by = blockIdx.y;
    int x = threadIdx.x, y = threadIdx.y;
    #pragma unroll
    for (int j = 0; j < 32; j += 8)
        t[y + j][x] = Wsrc[(by * 32 + y + j) * 512 + bx * 32 + x];
    __syncthreads();
    #pragma unroll
    for (int j = 0; j < 32; j += 8) {
        float v = t[x][y + j];
        int n = bx * 32 + y + j;
        int k = by * 32 + x;
        __nv_bfloat16 hv = __float2bfloat16_rn(v);
        hz[n * 512 + k] = hv;
        lz[n * 512 + k] = __float2bfloat16_rn(v - __bfloat162float(hv));
    }
}

__global__ void biascat(Ptr8 bsrc, float* __restrict__ dst) {
    int i = blockIdx.x * 256 + threadIdx.x;
    dst[i] = bsrc.p[i >> 9][i & 511];
}

// ---------------------------------------------------------------------------
// Tensor-core GEMM: C[8192,N] = A[8192,512] @ Wt[N,512]^T + bias
// 3-term bf16 split; ldmatrix; 128x128x32 tiles, 2-stage cp.async,
// SINGLE __syncthreads per K-iteration (loads overlap MMAs).
// ---------------------------------------------------------------------------
#define SMEM_STAGE 20480                  // bf16 elems per stage
#define SMEM_BYTES (2 * SMEM_STAGE * 2)   // 81920 B

__device__ __forceinline__ void mma16816(float* d, const uint32_t* a,
                                         const uint32_t* b) {
    asm volatile("mma.sync.aligned.m16n8k16.row.col.f32.bf16.bf16.f32 "
                 "{%0,%1,%2,%3}, {%4,%5,%6,%7}, {%8,%9}, {%0,%1,%2,%3};"
                 : "+f"(d[0]), "+f"(d[1]), "+f"(d[2]), "+f"(d[3])
                 : "r"(a[0]), "r"(a[1]), "r"(a[2]), "r"(a[3]),
                   "r"(b[0]), "r"(b[1]));
}

__device__ __forceinline__ void ldsm_x4(uint32_t* r, uint32_t a) {
    asm volatile("ldmatrix.sync.aligned.m8n8.x4.shared.b16 {%0,%1,%2,%3}, [%4];"
                 : "=r"(r[0]), "=r"(r[1]), "=r"(r[2]), "=r"(r[3]) : "r"(a));
}

__global__ void __launch_bounds__(256, 2)
mma_gemm(const __nv_bfloat16* __restrict__ Ahi, const __nv_bfloat16* __restrict__ Alo,
         const __nv_bfloat16* __restrict__ Whi, const __nv_bfloat16* __restrict__ Wlo,
         const float* __restrict__ bias, float* __restrict__ C, int ldc) {
    extern __shared__ __nv_bfloat16 sm[];
    const int tid  = threadIdx.x;
    const int lane = tid & 31;
    const int warp = tid >> 5;
    const int wm = warp >> 2;        // 0..1
    const int wn = warp & 3;         // 0..3
    const int m0 = blockIdx.y * 128;
    const int n0 = blockIdx.x * 128;

    float acc[4][4][4];
    #pragma unroll
    for (int i = 0; i < 4; i++)
        #pragma unroll
        for (int j = 0; j < 4; j++)
            #pragma unroll
            for (int t = 0; t < 4; t++) acc[i][j][t] = 0.f;

    uint32_t smbase = (uint32_t)__cvta_generic_to_shared(sm);

    auto load_stage = [&](int s, int k0) {
        uint32_t base = smbase + (uint32_t)(s * SMEM_STAGE * 2);
        #pragma unroll
        for (int i = 0; i < 2; i++) {
            int id  = tid + i * 256;
            int row = id >> 2;
            int qc  = (id & 3) << 3;
            uint32_t so = base + (uint32_t)((row * 40 + qc) * 2);
            const __nv_bfloat16* ga = Ahi + (m0 + row) * 512 + k0 + qc;
            const __nv_bfloat16* gb = Alo + (m0 + row) * 512 + k0 + qc;
            const __nv_bfloat16* gc = Whi + (n0 + row) * 512 + k0 + qc;
            const __nv_bfloat16* gd = Wlo + (n0 + row) * 512 + k0 + qc;
            asm volatile("cp.async.cg.shared.global [%0], [%1], 16;" :: "r"(so),           "l"(ga));
            asm volatile("cp.async.cg.shared.global [%0], [%1], 16;" :: "r"(so + 10240u), "l"(gb));
            asm volatile("cp.async.cg.shared.global [%0], [%1], 16;" :: "r"(so + 20480u), "l"(gc));
            asm volatile("cp.async.cg.shared.global [%0], [%1], 16;" :: "r"(so + 30720u), "l"(gd));
        }
    };

    load_stage(0, 0);
    asm volatile("cp.async.commit_group;");

    const int lrow  = lane & 15;
    const int lkoff = (lane >> 4) << 3;

    #pragma unroll 1
    for (int it = 0; it < 16; it++) {
        // Stage it&1 ready; sync also orders last iter's reads of stage
        // (it+1)&1 before this iter's writes to it.
        asm volatile("cp.async.wait_group 0;");
        __syncthreads();
        if (it < 15) {
            load_stage((it + 1) & 1, (it + 1) * 32);
            asm volatile("cp.async.commit_group;");
        }

        uint32_t st = smbase + (uint32_t)((it & 1) * SMEM_STAGE * 2);

        #pragma unroll
        for (int ks = 0; ks < 2; ks++) {
            int col = ks * 16 + lkoff;
            uint32_t bh[4][2], bl[4][2];
            #pragma unroll
            for (int ntp = 0; ntp < 2; ntp++) {
                int n = wn * 32 + ntp * 16 + lrow;
                uint32_t adr = st + 20480u + (uint32_t)((n * 40 + col) * 2);
                uint32_t t4[4];
                ldsm_x4(t4, adr);
                bh[ntp * 2 + 0][0] = t4[0]; bh[ntp * 2 + 0][1] = t4[2];
                bh[ntp * 2 + 1][0] = t4[1]; bh[ntp * 2 + 1][1] = t4[3];
                ldsm_x4(t4, adr + 10240u);
                bl[ntp * 2 + 0][0] = t4[0]; bl[ntp * 2 + 0][1] = t4[2];
                bl[ntp * 2 + 1][0] = t4[1]; bl[ntp * 2 + 1][1] = t4[3];
            }
            #pragma unroll
            for (int mt = 0; mt < 4; mt++) {
                int row = wm * 64 + mt * 16 + lrow;
                uint32_t adr = st + (uint32_t)((row * 40 + col) * 2);
                uint32_t ah[4], al[4];
                ldsm_x4(ah, adr);
                ldsm_x4(al, adr + 10240u);
                #pragma unroll
                for (int nt = 0; nt < 4; nt++) {
                    mma16816(acc[mt][nt], ah, bh[nt]);
                    mma16816(acc[mt][nt], ah, bl[nt]);
                    mma16816(acc[mt][nt], al, bh[nt]);
                }
            }
        }
    }

    const int r = lane >> 2;
    const int c = (lane & 3) << 1;
    #pragma unroll
    for (int mt = 0; mt < 4; mt++) {
        #pragma unroll
        for (int nt = 0; nt < 4; nt++) {
            int row = m0 + wm * 64 + mt * 16 + r;
            int col = n0 + wn * 32 + nt * 8 + c;
            float b0 = bias[col], b1 = bias[col + 1];
            float2 v0 = make_float2(acc[mt][nt][0] + b0, acc[mt][nt][1] + b1);
            float2 v1 = make_float2(acc[mt][nt][2] + b0, acc[mt][nt][3] + b1);
            *(float2*)(C + row * ldc + col)       = v0;
            *(float2*)(C + (row + 8) * ldc + col) = v1;
        }
    }
}

// ---------------------------------------------------------------------------
// Small GEMM, K-split (deterministic 2-phase):
// phase 1: grid (8 kchunks, njobs) — partial C for K range [kc*64, kc*64+64)
// phase 2: grid (32, njobs)        — sum 8 partials + bias -> C
// ---------------------------------------------------------------------------
__global__ void __launch_bounds__(256)
sgemm16_part(const float* __restrict__ A, SJobs jobs, float* __restrict__ part) {
    __shared__ float As[16][64];
    int kc  = blockIdx.x;
    int job = blockIdx.y;
    int tid = threadIdx.x;
    for (int i = tid; i < 16 * 64; i += 256) {
        int r = i >> 6, kk = i & 63;
        As[r][kk] = A[r * 512 + kc * 64 + kk];
    }
    __syncthreads();
    const float* W = jobs.W[job] + (size_t)(kc * 64) * 512;
    float acc0[16], acc1[16];
    #pragma unroll
    for (int r = 0; r < 16; r++) { acc0[r] = 0.f; acc1[r] = 0.f; }
    #pragma unroll 4
    for (int kk = 0; kk < 64; kk++) {
        float w0 = W[kk * 512 + tid];
        float w1 = W[kk * 512 + tid + 256];
        #pragma unroll
        for (int r = 0; r < 16; r++) {
            float a = As[r][kk];
            acc0[r] = fmaf(a, w0, acc0[r]);
            acc1[r] = fmaf(a, w1, acc1[r]);
        }
    }
    float* p = part + ((size_t)job * 8 + kc) * (16 * 512);
    #pragma unroll
    for (int r = 0; r < 16; r++) {
        p[r * 512 + tid]       = acc0[r];
        p[r * 512 + tid + 256] = acc1[r];
    }
}

__global__ void __launch_bounds__(256)
sgemm16_red(SJobs jobs, const float* __restrict__ part) {
    int job = blockIdx.y;
    int i   = blockIdx.x * 256 + threadIdx.x;   // 0..8191
    int c   = i & 511;
    const float* p = part + (size_t)job * 8 * (16 * 512) + i;
    float v = jobs.bias[job][c];
    #pragma unroll
    for (int kc = 0; kc < 8; kc++) v += p[kc * (16 * 512)];
    jobs.C[job][i] = v;
}

// ---------------------------------------------------------------------------
// sat attention: 5 keys per token; generalized source pointers/strides
// ---------------------------------------------------------------------------
__global__ void sat_attn(const float* __restrict__ Q,  int ldq,
                         const float* __restrict__ Kh, const float* __restrict__ Vh,
                         int ldkv,
                         const float* __restrict__ Ke, const float* __restrict__ Ve,
                         int ldke,
                         const float* __restrict__ Ks,  const float* __restrict__ Vs,
                         __nv_bfloat16* __restrict__ chi, __nv_bfloat16* __restrict__ clo) {
    int t = blockIdx.x;
    int b = t >> 9;
    int l = t & 511;
    int head = threadIdx.x >> 5;
    int lane = threadIdx.x & 31;
    int d0 = head * HD + lane;
    int r0 = (b << 9) + ((l + 1) & 511);
    int r2 = (b << 9) + (l == 0 ? (L - 1) : 0);

    const float* qp = Q + (size_t)t * ldq + d0;
    float q0 = qp[0], q1 = qp[32];
    const float* kp[5] = { Kh + (size_t)r0 * ldkv + d0, Kh + (size_t)t * ldkv + d0,
                           Kh + (size_t)r2 * ldkv + d0, Ke + (size_t)t * ldke + d0,
                           Ks + b * D + d0 };
    const float* vp[5] = { Vh + (size_t)r0 * ldkv + d0, Vh + (size_t)t * ldkv + d0,
                           Vh + (size_t)r2 * ldkv + d0, Ve + (size_t)t * ldke + d0,
                           Vs + b * D + d0 };
    float sc[5];
    #pragma unroll
    for (int i = 0; i < 5; i++) {
        float p = q0 * kp[i][0] + q1 * kp[i][32];
        #pragma unroll
        for (int o = 16; o > 0; o >>= 1) p += __shfl_xor_sync(0xffffffffu, p, o);
        sc[i] = p * 0.125f;
    }
    float m = sc[0];
    #pragma unroll
    for (int i = 1; i < 5; i++) m = fmaxf(m, sc[i]);
    float den = 0.f;
    #pragma unroll
    for (int i = 0; i < 5; i++) { sc[i] = expf(sc[i] - m); den += sc[i]; }
    float inv = 1.f / den;
    float o0 = 0.f, o1 = 0.f;
    #pragma unroll
    for (int i = 0; i < 5; i++) {
        o0 = fmaf(sc[i], vp[i][0],  o0);
        o1 = fmaf(sc[i], vp[i][32], o1);
    }
    o0 *= inv; o1 *= inv;
    int base = t * D;
    __nv_bfloat16 h0 = __float2bfloat16_rn(o0);
    __nv_bfloat16 h1 = __float2bfloat16_rn(o1);
    chi[base + d0]      = h0;
    chi[base + d0 + 32] = h1;
    clo[base + d0]      = __float2bfloat16_rn(o0 - __bfloat162float(h0));
    clo[base + d0 + 32] = __float2bfloat16_rn(o1 - __bfloat162float(h1));
}

// ---------------------------------------------------------------------------
// rel attention: 513 keys
// ---------------------------------------------------------------------------
__global__ void rel_attn(const float* __restrict__ Qs,  const float* __restrict__ Ksr,
                         const float* __restrict__ KrVr, const float* __restrict__ Vsr,
                         float* __restrict__ ctxs) {
    __shared__ float sc[513];
    __shared__ float red[256];
    __shared__ float qsh[HD];
    int b    = blockIdx.x >> 3;
    int head = blockIdx.x & 7;
    int tid  = threadIdx.x;
    int off  = head * HD;

    if (tid < HD) qsh[tid] = Qs[b * D + off + tid];
    __syncthreads();

    for (int k = tid; k < 513; k += 256) {
        const float* kv = (k == 0) ? (Ksr + b * D + off)
                                   : (KrVr + ((b << 9) + k - 1) * 1024 + off);
        float p = 0.f;
        #pragma unroll
        for (int d = 0; d < HD; d++) p = fmaf(qsh[d], kv[d], p);
        sc[k] = p * 0.125f;
    }
    __syncthreads();

    float m = -1e30f;
    for (int k = tid; k < 513; k += 256) m = fmaxf(m, sc[k]);
    red[tid] = m; __syncthreads();
    for (int st = 128; st > 0; st >>= 1) {
        if (tid < st) red[tid] = fmaxf(red[tid], red[tid + st]);
        __syncthreads();
    }
    m = red[0];
    __syncthreads();

    float dsum = 0.f;
    for (int k = tid; k < 513; k += 256) {
        float e_ = expf(sc[k] - m);
        sc[k] = e_;
        dsum += e_;
    }
    red[tid] = dsum; __syncthreads();
    for (int st = 128; st > 0; st >>= 1) {
        if (tid < st) red[tid] += red[tid + st];
        __syncthreads();
    }
    float inv = 1.f / red[0];
    __syncthreads();

    int d = tid & 63;
    int g = tid >> 6;
    float acc = 0.f;
    for (int k = g; k < 513; k += 4) {
        const float* vv = (k == 0) ? (Vsr + b * D + off)
                                   : (KrVr + ((b << 9) + k - 1) * 1024 + 512 + off);
        acc = fmaf(sc[k], vv[d], acc);
    }
    red[tid] = acc;
    __syncthreads();
    if (tid < 64) {
        float o = red[tid] + red[tid + 64] + red[tid + 128] + red[tid + 192];
        ctxs[b * D + off + tid] = o * inv;
    }
}

// ---------------------------------------------------------------------------
// relu + LayerNorm (+ optional bf16 split outputs)
// ---------------------------------------------------------------------------
__global__ void relu_ln(const float* __restrict__ x, const float* __restrict__ w,
                        const float* __restrict__ bb, float* __restrict__ out,
                        __nv_bfloat16* __restrict__ hi, __nv_bfloat16* __restrict__ lo) {
    __shared__ float red[256];
    int row = blockIdx.x;
    int tid = threadIdx.x;
    float v0 = fmaxf(x[row * D + tid],       0.f);
    float v1 = fmaxf(x[row * D + tid + 256], 0.f);
    red[tid] = v0 + v1;
    __syncthreads();
    for (int st = 128; st > 0; st >>= 1) {
        if (tid < st) red[tid] += red[tid + st];
        __syncthreads();
    }
    float mean = red[0] * (1.f / 512.f);
    __syncthreads();
    float d0 = v0 - mean, d1 = v1 - mean;
    red[tid] = d0 * d0 + d1 * d1;
    __syncthreads();
    for (int st = 128; st > 0; st >>= 1) {
        if (tid < st) red[tid] += red[tid + st];
        __syncthreads();
    }
    float inv = rsqrtf(red[0] * (1.f / 512.f) + 1e-12f);
    float o0 = w[tid]       * d0 * inv + bb[tid];
    float o1 = w[tid + 256] * d1 * inv + bb[tid + 256];
    out[row * D + tid]       = o0;
    out[row * D + tid + 256] = o1;
    if (hi) {
        __nv_bfloat16 h0 = __float2bfloat16_rn(o0);
        __nv_bfloat16 h1 = __float2bfloat16_rn(o1);
        hi[row * D + tid]       = h0;
        hi[row * D + tid + 256] = h1;
        lo[row * D + tid]       = __float2bfloat16_rn(o0 - __bfloat162float(h0));
        lo[row * D + tid + 256] = __float2bfloat16_rn(o1 - __bfloat162float(h1));
    }
}

// ---------------------------------------------------------------------------
// logits = h @ ofc_w[512,17] + ofc_b
// ---------------------------------------------------------------------------
__global__ void final_logits(const float* __restrict__ h, const float* __restrict__ W,
                             const float* __restrict__ bias, float* __restrict__ out) {
    __shared__ float Wsh[512 * T];
    int tid = threadIdx.x;
    for (int i = tid; i < 512 * T; i += 256) Wsh[i] = W[i];
    __syncthreads();
    int warp = tid >> 5, lane = tid & 31;
    int row = blockIdx.x * 8 + warp;
    float acc[T];
    #pragma unroll
    for (int t = 0; t < T; t++) acc[t] = 0.f;
    const float* hr = h + row * D;
    for (int k = lane; k < D; k += 32) {
        float a = hr[k];
        #pragma unroll
        for (int t = 0; t < T; t++) acc[t] = fmaf(a, Wsh[k * T + t], acc[t]);
    }
    #pragma unroll
    for (int t = 0; t < T; t++)
        #pragma unroll
        for (int o = 16; o > 0; o >>= 1)
            acc[t] += __shfl_xor_sync(0xffffffffu, acc[t], o);
    if (lane == 0) {
        #pragma unroll
        for (int t = 0; t < T; t++) out[row * T + t] = acc[t] + bias[t];
    }
}

// ---------------------------------------------------------------------------
// Launch
// ---------------------------------------------------------------------------
extern "C" void kernel_launch(void* const* d_in, const int* in_sizes, int n_in,
                              void* d_out, int out_size) {
    (void)in_sizes; (void)n_in; (void)out_size;
    const int*   tokens  = (const int*)  d_in[0];
    const float* emb     = (const float*)d_in[4];
    Ptr8 wsrc = {{ (const float*)d_in[5],  (const float*)d_in[7],
                   (const float*)d_in[9],  (const float*)d_in[11],
                   (const float*)d_in[13], (const float*)d_in[15],
                   (const float*)d_in[17], (const float*)d_in[19] }};
    Ptr8 bsrc = {{ (const float*)d_in[6],  (const float*)d_in[8],
                   (const float*)d_in[10], (const float*)d_in[12],
                   (const float*)d_in[14], (const float*)d_in[16],
                   (const float*)d_in[18], (const float*)d_in[20] }};
    const float* sat_kw = (const float*)d_in[7];
    const float* sat_kb = (const float*)d_in[8];
    const float* sat_vw = (const float*)d_in[9];
    const float* sat_vb = (const float*)d_in[10];
    const float* rel_qw = (const float*)d_in[13];
    const float* rel_qb = (const float*)d_in[14];
    const float* rel_kw = (const float*)d_in[15];
    const float* rel_kb = (const float*)d_in[16];
    const float* rel_vw = (const float*)d_in[17];
    const float* rel_vb = (const float*)d_in[18];
    const float* rel_ow = (const float*)d_in[19];
    const float* rel_ob = (const float*)d_in[20];
    const float* ln_sw  = (const float*)d_in[21];
    const float* ln_sb  = (const float*)d_in[22];
    const float* ln_rw  = (const float*)d_in[23];
    const float* ln_rb  = (const float*)d_in[24];
    const float* ofc_w  = (const float*)d_in[25];
    const float* ofc_b  = (const float*)d_in[26];
    float* out = (float*)d_out;

    float *e, *h, *s, *qkv, *keve, *krvr, *a;
    float *ks, *vs, *qsr, *ksr, *vsr, *ctxs, *r, *bias, *part;
    __nv_bfloat16 *ehi, *elo, *hhi, *hlo, *cthi, *ctlo, *whi, *wlo;
    cudaGetSymbolAddress((void**)&e,    g_e);
    cudaGetSymbolAddress((void**)&h,    g_h);
    cudaGetSymbolAddress((void**)&s,    g_s);
    cudaGetSymbolAddress((void**)&qkv,  g_qkv);
    cudaGetSymbolAddress((void**)&keve, g_keve);
    cudaGetSymbolAddress((void**)&krvr, g_krvr);
    cudaGetSymbolAddress((void**)&a,    g_a);
    cudaGetSymbolAddress((void**)&ks,   g_ks);
    cudaGetSymbolAddress((void**)&vs,   g_vs);
    cudaGetSymbolAddress((void**)&qsr,  g_qsr);
    cudaGetSymbolAddress((void**)&ksr,  g_ksr);
    cudaGetSymbolAddress((void**)&vsr,  g_vsr);
    cudaGetSymbolAddress((void**)&ctxs, g_ctxs);
    cudaGetSymbolAddress((void**)&r,    g_r);
    cudaGetSymbolAddress((void**)&bias, g_bias);
    cudaGetSymbolAddress((void**)&part, g_part);
    cudaGetSymbolAddress((void**)&ehi,  g_ehi);
    cudaGetSymbolAddress((void**)&elo,  g_elo);
    cudaGetSymbolAddress((void**)&hhi,  g_hhi);
    cudaGetSymbolAddress((void**)&hlo,  g_hlo);
    cudaGetSymbolAddress((void**)&cthi, g_cthi);
    cudaGetSymbolAddress((void**)&ctlo, g_ctlo);
    cudaGetSymbolAddress((void**)&whi,  g_whi);
    cudaGetSymbolAddress((void**)&wlo,  g_wlo);

    cudaFuncSetAttribute(mma_gemm, cudaFuncAttributeMaxDynamicSharedMemorySize,
                         SMEM_BYTES);

    #define GEMM(AHI, ALO, WI, NTOT, OUT, LDC)                                 \
        mma_gemm<<<dim3((NTOT) / 128, 64), 256, SMEM_BYTES>>>(                 \
            AHI, ALO, whi + (WI) * DD, wlo + (WI) * DD, bias + (WI) * 512,     \
            OUT, LDC)

    #define SMALL(AIN, JOBS, NJ)                                               \
        do {                                                                   \
            sgemm16_part<<<dim3(8, NJ), 256>>>(AIN, JOBS, part);               \
            sgemm16_red<<<dim3(32, NJ), 256>>>(JOBS, part);                    \
        } while (0)

    // Weight prep
    wsplit_all<<<dim3(16, 16, 8), dim3(32, 8)>>>(wsrc, whi, wlo);
    biascat<<<16, 256>>>(bsrc, bias);

    embed_split<<<BL * D / 256, 256>>>(tokens, emb, e, ehi, elo);

    // e-projections first (keeps mma_gemm in ncu's capture slot)
    GEMM(ehi, elo, 1, 1024, keve, 1024);

    smean_kernel<<<B * 8, 256>>>(e, s);

    for (int c = 0; c < CYC; c++) {
        const bool last = (c == CYC - 1);

        {
            SJobs j = {{ sat_kw, sat_vw, nullptr },
                       { sat_kb, sat_vb, nullptr },
                       { ks, vs, nullptr }};
            SMALL(s, j, 2);
        }

        if (c == 0) {
            // h == e: K(h), V(h) identical to keve — only q is new.
            GEMM(ehi, elo, 0, 512, qkv, 512);
            sat_attn<<<BL, 256>>>(qkv, 512,
                                  keve, keve + 512, 1024,
                                  keve, keve + 512, 1024,
                                  ks, vs, cthi, ctlo);
        } else {
            GEMM(hhi, hlo, 0, 1536, qkv, 1536);   // q | k | v
            sat_attn<<<BL, 256>>>(qkv, 1536,
                                  qkv + 512, qkv + 1024, 1536,
                                  keve, keve + 512, 1024,
                                  ks, vs, cthi, ctlo);
        }

        GEMM(cthi, ctlo, 3, 512, a, 512);         // sat_o
        relu_ln<<<BL, 256>>>(a, ln_sw, ln_sb, h,
                             last ? nullptr : hhi, last ? nullptr : hlo);

        // rel path is dead on the final cycle (s never consumed again)
        if (!last) {
            GEMM(hhi, hlo, 5, 1024, krvr, 1024);  // rel_k | rel_v
            {
                SJobs j = {{ rel_qw, rel_kw, rel_vw },
                           { rel_qb, rel_kb, rel_vb },
                           { qsr, ksr, vsr }};
                SMALL(s, j, 3);
            }

            rel_attn<<<B * NH, 256>>>(qsr, ksr, krvr, vsr, ctxs);
            {
                SJobs j = {{ rel_ow, nullptr, nullptr },
                           { rel_ob, nullptr, nullptr },
                           { r, nullptr, nullptr }};
                SMALL(ctxs, j, 1);
            }
            relu_ln<<<B, 256>>>(r, ln_rw, ln_rb, s, nullptr, nullptr);
        }
    }

    final_logits<<<BL / 8, 256>>>(h, ofc_w, ofc_b, out);
}

// round 11
// speedup vs baseline: 2.0165x; 1.0034x over previous
#include <cuda_runtime.h>
#include <cuda_bf16.h>
#include <cstdint>
#include <math.h>

// Problem constants
#define B   16
#define L   512
#define D   512
#define NH  8
#define HD  64
#define T   17
#define CYC 2
#define BL  (B * L)   // 8192
#define DD  (D * D)

// ---------------------------------------------------------------------------
// Scratch (device globals)
// ---------------------------------------------------------------------------
__device__ float g_e[BL * D];
__device__ float g_h[BL * D];
__device__ float g_s[B * D];
__device__ float g_qkv[BL * 1536];    // cyc1: q | k | v
__device__ float g_qkeve[BL * 1536];  // cyc0: q | ke | ve  (ke/ve reused by cyc1)
__device__ float g_krvr[BL * 1024];   // kr | vr
__device__ float g_a[BL * D];
__device__ float g_ks[B * D];
__device__ float g_vs[B * D];
__device__ float g_qsr[B * D];
__device__ float g_ksr[B * D];
__device__ float g_vsr[B * D];
__device__ float g_ctxs[B * D];
__device__ float g_r[B * D];
__device__ float g_bias[8 * D];      // concatenated biases, weight order
__device__ float g_part[3 * 8 * 16 * 512];   // small-gemm K-split partials

// bf16 split buffers (16B aligned for cp.async 16)
__device__ __align__(16) __nv_bfloat16 g_ehi[BL * D];
__device__ __align__(16) __nv_bfloat16 g_elo[BL * D];
__device__ __align__(16) __nv_bfloat16 g_hhi[BL * D];
__device__ __align__(16) __nv_bfloat16 g_hlo[BL * D];
__device__ __align__(16) __nv_bfloat16 g_cthi[BL * D];
__device__ __align__(16) __nv_bfloat16 g_ctlo[BL * D];
__device__ __align__(16) __nv_bfloat16 g_whi[8 * DD];   // transposed [N][K]
__device__ __align__(16) __nv_bfloat16 g_wlo[8 * DD];

struct Ptr8 { const float* p[8]; };
struct SJobs { const float* W[3]; const float* bias[3]; float* C[3]; };

// ---------------------------------------------------------------------------
// Embedding: e fp32 + split bf16
// ---------------------------------------------------------------------------
__global__ void embed_split(const int* __restrict__ tokens,
                            const float* __restrict__ emb,
                            float* __restrict__ e,
                            __nv_bfloat16* __restrict__ hi,
                            __nv_bfloat16* __restrict__ lo) {
    int idx = blockIdx.x * 256 + threadIdx.x;
    int row = idx / D;
    int d   = idx - row * D;
    float v = emb[tokens[row] * D + d];
    e[idx] = v;
    __nv_bfloat16 hv = __float2bfloat16_rn(v);
    hi[idx] = hv;
    lo[idx] = __float2bfloat16_rn(v - __bfloat162float(hv));
}

// s[b,d] = mean_l e[b,l,d] — grid = B*8, block 256
__global__ void smean_kernel(const float* __restrict__ e, float* __restrict__ s) {
    __shared__ float red[256];
    int b     = blockIdx.x >> 3;
    int dbase = (blockIdx.x & 7) * 64;
    int tid   = threadIdx.x;
    int d     = dbase + (tid & 63);
    int grp   = tid >> 6;
    const float* p = e + ((b << 9) + grp * 128) * D + d;
    float acc = 0.f;
    #pragma unroll 8
    for (int l = 0; l < 128; l++) acc += p[l * D];
    red[tid] = acc;
    __syncthreads();
    if (tid < 128) red[tid] += red[tid + 128];
    __syncthreads();
    if (tid < 64)
        s[b * D + d] = (red[tid] + red[tid + 64]) * (1.f / (float)L);
}

// ---------------------------------------------------------------------------
// Weight prep: split + transpose all 8 weights; concat biases
// ---------------------------------------------------------------------------
__global__ void wsplit_all(Ptr8 W, __nv_bfloat16* __restrict__ hi,
                           __nv_bfloat16* __restrict__ lo) {
    __shared__ float t[32][33];
    const float* Wsrc = W.p[blockIdx.z];
    __nv_bfloat16* hz = hi + blockIdx.z * DD;
    __nv_bfloat16* lz = lo + blockIdx.z * DD;
    int bx = blockIdx.x, by = blockIdx.y;
    int x = threadIdx.x, y = threadIdx.y;
    #pragma unroll
    for (int j = 0; j < 32; j += 8)
        t[y + j][x] = Wsrc[(by * 32 + y + j) * 512 + bx * 32 + x];
    __syncthreads();
    #pragma unroll
    for (int j = 0; j < 32; j += 8) {
        float v = t[x][y + j];
        int n = bx * 32 + y + j;
        int k = by * 32 + x;
        __nv_bfloat16 hv = __float2bfloat16_rn(v);
        hz[n * 512 + k] = hv;
        lz[n * 512 + k] = __float2bfloat16_rn(v - __bfloat162float(hv));
    }
}

__global__ void biascat(Ptr8 bsrc, float* __restrict__ dst) {
    int i = blockIdx.x * 256 + threadIdx.x;
    dst[i] = bsrc.p[i >> 9][i & 511];
}

// ---------------------------------------------------------------------------
// Tensor-core GEMM: C[8192,N] = A[8192,512] @ Wt[N,512]^T + bias
// 3-term bf16 split; ldmatrix; 128x128x32 tiles, 2-stage cp.async,
// single sync per K-iter, WARP PHASE STAGGER (odd warps do ks=1 first)
// so LDSM bursts of one warp group overlap MMA bursts of the other.
// ---------------------------------------------------------------------------
#define SMEM_STAGE 20480                  // bf16 elems per stage
#define SMEM_BYTES (2 * SMEM_STAGE * 2)   // 81920 B

__device__ __forceinline__ void mma16816(float* d, const uint32_t* a,
                                         const uint32_t* b) {
    asm volatile("mma.sync.aligned.m16n8k16.row.col.f32.bf16.bf16.f32 "
                 "{%0,%1,%2,%3}, {%4,%5,%6,%7}, {%8,%9}, {%0,%1,%2,%3};"
                 : "+f"(d[0]), "+f"(d[1]), "+f"(d[2]), "+f"(d[3])
                 : "r"(a[0]), "r"(a[1]), "r"(a[2]), "r"(a[3]),
                   "r"(b[0]), "r"(b[1]));
}

__device__ __forceinline__ void ldsm_x4(uint32_t* r, uint32_t a) {
    asm volatile("ldmatrix.sync.aligned.m8n8.x4.shared.b16 {%0,%1,%2,%3}, [%4];"
                 : "=r"(r[0]), "=r"(r[1]), "=r"(r[2]), "=r"(r[3]) : "r"(a));
}

__global__ void __launch_bounds__(256, 2)
mma_gemm(const __nv_bfloat16* __restrict__ Ahi, const __nv_bfloat16* __restrict__ Alo,
         const __nv_bfloat16* __restrict__ Whi, const __nv_bfloat16* __restrict__ Wlo,
         const float* __restrict__ bias, float* __restrict__ C, int ldc) {
    extern __shared__ __nv_bfloat16 sm[];
    const int tid  = threadIdx.x;
    const int lane = tid & 31;
    const int warp = tid >> 5;
    const int wm = warp >> 2;        // 0..1
    const int wn = warp & 3;         // 0..3
    const int m0 = blockIdx.y * 128;
    const int n0 = blockIdx.x * 128;
    const int sks = warp & 1;        // phase stagger

    float acc[4][4][4];
    #pragma unroll
    for (int i = 0; i < 4; i++)
        #pragma unroll
        for (int j = 0; j < 4; j++)
            #pragma unroll
            for (int t = 0; t < 4; t++) acc[i][j][t] = 0.f;

    uint32_t smbase = (uint32_t)__cvta_generic_to_shared(sm);

    auto load_stage = [&](int s, int k0) {
        uint32_t base = smbase + (uint32_t)(s * SMEM_STAGE * 2);
        #pragma unroll
        for (int i = 0; i < 2; i++) {
            int id  = tid + i * 256;
            int row = id >> 2;
            int qc  = (id & 3) << 3;
            uint32_t so = base + (uint32_t)((row * 40 + qc) * 2);
            const __nv_bfloat16* ga = Ahi + (m0 + row) * 512 + k0 + qc;
            const __nv_bfloat16* gb = Alo + (m0 + row) * 512 + k0 + qc;
            const __nv_bfloat16* gc = Whi + (n0 + row) * 512 + k0 + qc;
            const __nv_bfloat16* gd = Wlo + (n0 + row) * 512 + k0 + qc;
            asm volatile("cp.async.cg.shared.global [%0], [%1], 16;" :: "r"(so),           "l"(ga));
            asm volatile("cp.async.cg.shared.global [%0], [%1], 16;" :: "r"(so + 10240u), "l"(gb));
            asm volatile("cp.async.cg.shared.global [%0], [%1], 16;" :: "r"(so + 20480u), "l"(gc));
            asm volatile("cp.async.cg.shared.global [%0], [%1], 16;" :: "r"(so + 30720u), "l"(gd));
        }
    };

    load_stage(0, 0);
    asm volatile("cp.async.commit_group;");

    const int lrow  = lane & 15;
    const int lkoff = (lane >> 4) << 3;

    #pragma unroll 1
    for (int it = 0; it < 16; it++) {
        asm volatile("cp.async.wait_group 0;");
        __syncthreads();
        if (it < 15) {
            load_stage((it + 1) & 1, (it + 1) * 32);
            asm volatile("cp.async.commit_group;");
        }

        uint32_t st = smbase + (uint32_t)((it & 1) * SMEM_STAGE * 2);

        #pragma unroll
        for (int s = 0; s < 2; s++) {
            int ks = s ^ sks;                 // staggered across warps
            int col = ks * 16 + lkoff;
            uint32_t bh[4][2], bl[4][2];
            #pragma unroll
            for (int ntp = 0; ntp < 2; ntp++) {
                int n = wn * 32 + ntp * 16 + lrow;
                uint32_t adr = st + 20480u + (uint32_t)((n * 40 + col) * 2);
                uint32_t t4[4];
                ldsm_x4(t4, adr);
                bh[ntp * 2 + 0][0] = t4[0]; bh[ntp * 2 + 0][1] = t4[2];
                bh[ntp * 2 + 1][0] = t4[1]; bh[ntp * 2 + 1][1] = t4[3];
                ldsm_x4(t4, adr + 10240u);
                bl[ntp * 2 + 0][0] = t4[0]; bl[ntp * 2 + 0][1] = t4[2];
                bl[ntp * 2 + 1][0] = t4[1]; bl[ntp * 2 + 1][1] = t4[3];
            }
            #pragma unroll
            for (int mt = 0; mt < 4; mt++) {
                int row = wm * 64 + mt * 16 + lrow;
                uint32_t adr = st + (uint32_t)((row * 40 + col) * 2);
                uint32_t ah[4], al[4];
                ldsm_x4(ah, adr);
                ldsm_x4(al, adr + 10240u);
                #pragma unroll
                for (int nt = 0; nt < 4; nt++) {
                    mma16816(acc[mt][nt], ah, bh[nt]);
                    mma16816(acc[mt][nt], ah, bl[nt]);
                    mma16816(acc[mt][nt], al, bh[nt]);
                }
            }
        }
    }

    const int r = lane >> 2;
    const int c = (lane & 3) << 1;
    #pragma unroll
    for (int mt = 0; mt < 4; mt++) {
        #pragma unroll
        for (int nt = 0; nt < 4; nt++) {
            int row = m0 + wm * 64 + mt * 16 + r;
            int col = n0 + wn * 32 + nt * 8 + c;
            float b0 = bias[col], b1 = bias[col + 1];
            float2 v0 = make_float2(acc[mt][nt][0] + b0, acc[mt][nt][1] + b1);
            float2 v1 = make_float2(acc[mt][nt][2] + b0, acc[mt][nt][3] + b1);
            *(float2*)(C + row * ldc + col)       = v0;
            *(float2*)(C + (row + 8) * ldc + col) = v1;
        }
    }
}

// ---------------------------------------------------------------------------
// Small GEMM, K-split 2-phase (deterministic)
// ---------------------------------------------------------------------------
__global__ void __launch_bounds__(256)
sgemm16_part(const float* __restrict__ A, SJobs jobs, float* __restrict__ part) {
    __shared__ float As[16][64];
    int kc  = blockIdx.x;
    int job = blockIdx.y;
    int tid = threadIdx.x;
    for (int i = tid; i < 16 * 64; i += 256) {
        int r = i >> 6, kk = i & 63;
        As[r][kk] = A[r * 512 + kc * 64 + kk];
    }
    __syncthreads();
    const float* W = jobs.W[job] + (size_t)(kc * 64) * 512;
    float acc0[16], acc1[16];
    #pragma unroll
    for (int r = 0; r < 16; r++) { acc0[r] = 0.f; acc1[r] = 0.f; }
    #pragma unroll 4
    for (int kk = 0; kk < 64; kk++) {
        float w0 = W[kk * 512 + tid];
        float w1 = W[kk * 512 + tid + 256];
        #pragma unroll
        for (int r = 0; r < 16; r++) {
            float a = As[r][kk];
            acc0[r] = fmaf(a, w0, acc0[r]);
            acc1[r] = fmaf(a, w1, acc1[r]);
        }
    }
    float* p = part + ((size_t)job * 8 + kc) * (16 * 512);
    #pragma unroll
    for (int r = 0; r < 16; r++) {
        p[r * 512 + tid]       = acc0[r];
        p[r * 512 + tid + 256] = acc1[r];
    }
}

__global__ void __launch_bounds__(256)
sgemm16_red(SJobs jobs, const float* __restrict__ part) {
    int job = blockIdx.y;
    int i   = blockIdx.x * 256 + threadIdx.x;
    int c   = i & 511;
    const float* p = part + (size_t)job * 8 * (16 * 512) + i;
    float v = jobs.bias[job][c];
    #pragma unroll
    for (int kc = 0; kc < 8; kc++) v += p[kc * (16 * 512)];
    jobs.C[job][i] = v;
}

// ---------------------------------------------------------------------------
// sat attention: 5 keys per token; generalized source pointers/strides
// ---------------------------------------------------------------------------
__global__ void sat_attn(const float* __restrict__ Q,  int ldq,
                         const float* __restrict__ Kh, const float* __restrict__ Vh,
                         int ldkv,
                         const float* __restrict__ Ke, const float* __restrict__ Ve,
                         int ldke,
                         const float* __restrict__ Ks,  const float* __restrict__ Vs,
                         __nv_bfloat16* __restrict__ chi, __nv_bfloat16* __restrict__ clo) {
    int t = blockIdx.x;
    int b = t >> 9;
    int l = t & 511;
    int head = threadIdx.x >> 5;
    int lane = threadIdx.x & 31;
    int d0 = head * HD + lane;
    int r0 = (b << 9) + ((l + 1) & 511);
    int r2 = (b << 9) + (l == 0 ? (L - 1) : 0);

    const float* qp = Q + (size_t)t * ldq + d0;
    float q0 = qp[0], q1 = qp[32];
    const float* kp[5] = { Kh + (size_t)r0 * ldkv + d0, Kh + (size_t)t * ldkv + d0,
                           Kh + (size_t)r2 * ldkv + d0, Ke + (size_t)t * ldke + d0,
                           Ks + b * D + d0 };
    const float* vp[5] = { Vh + (size_t)r0 * ldkv + d0, Vh + (size_t)t * ldkv + d0,
                           Vh + (size_t)r2 * ldkv + d0, Ve + (size_t)t * ldke + d0,
                           Vs + b * D + d0 };
    float sc[5];
    #pragma unroll
    for (int i = 0; i < 5; i++) {
        float p = q0 * kp[i][0] + q1 * kp[i][32];
        #pragma unroll
        for (int o = 16; o > 0; o >>= 1) p += __shfl_xor_sync(0xffffffffu, p, o);
        sc[i] = p * 0.125f;
    }
    float m = sc[0];
    #pragma unroll
    for (int i = 1; i < 5; i++) m = fmaxf(m, sc[i]);
    float den = 0.f;
    #pragma unroll
    for (int i = 0; i < 5; i++) { sc[i] = expf(sc[i] - m); den += sc[i]; }
    float inv = 1.f / den;
    float o0 = 0.f, o1 = 0.f;
    #pragma unroll
    for (int i = 0; i < 5; i++) {
        o0 = fmaf(sc[i], vp[i][0],  o0);
        o1 = fmaf(sc[i], vp[i][32], o1);
    }
    o0 *= inv; o1 *= inv;
    int base = t * D;
    __nv_bfloat16 h0 = __float2bfloat16_rn(o0);
    __nv_bfloat16 h1 = __float2bfloat16_rn(o1);
    chi[base + d0]      = h0;
    chi[base + d0 + 32] = h1;
    clo[base + d0]      = __float2bfloat16_rn(o0 - __bfloat162float(h0));
    clo[base + d0 + 32] = __float2bfloat16_rn(o1 - __bfloat162float(h1));
}

// ---------------------------------------------------------------------------
// rel attention: 513 keys
// ---------------------------------------------------------------------------
__global__ void rel_attn(const float* __restrict__ Qs,  const float* __restrict__ Ksr,
                         const float* __restrict__ KrVr, const float* __restrict__ Vsr,
                         float* __restrict__ ctxs) {
    __shared__ float sc[513];
    __shared__ float red[256];
    __shared__ float qsh[HD];
    int b    = blockIdx.x >> 3;
    int head = blockIdx.x & 7;
    int tid  = threadIdx.x;
    int off  = head * HD;

    if (tid < HD) qsh[tid] = Qs[b * D + off + tid];
    __syncthreads();

    for (int k = tid; k < 513; k += 256) {
        const float* kv = (k == 0) ? (Ksr + b * D + off)
                                   : (KrVr + ((b << 9) + k - 1) * 1024 + off);
        float p = 0.f;
        #pragma unroll
        for (int d = 0; d < HD; d++) p = fmaf(qsh[d], kv[d], p);
        sc[k] = p * 0.125f;
    }
    __syncthreads();

    float m = -1e30f;
    for (int k = tid; k < 513; k += 256) m = fmaxf(m, sc[k]);
    red[tid] = m; __syncthreads();
    for (int st = 128; st > 0; st >>= 1) {
        if (tid < st) red[tid] = fmaxf(red[tid], red[tid + st]);
        __syncthreads();
    }
    m = red[0];
    __syncthreads();

    float dsum = 0.f;
    for (int k = tid; k < 513; k += 256) {
        float e_ = expf(sc[k] - m);
        sc[k] = e_;
        dsum += e_;
    }
    red[tid] = dsum; __syncthreads();
    for (int st = 128; st > 0; st >>= 1) {
        if (tid < st) red[tid] += red[tid + st];
        __syncthreads();
    }
    float inv = 1.f / red[0];
    __syncthreads();

    int d = tid & 63;
    int g = tid >> 6;
    float acc = 0.f;
    for (int k = g; k < 513; k += 4) {
        const float* vv = (k == 0) ? (Vsr + b * D + off)
                                   : (KrVr + ((b << 9) + k - 1) * 1024 + 512 + off);
        acc = fmaf(sc[k], vv[d], acc);
    }
    red[tid] = acc;
    __syncthreads();
    if (tid < 64) {
        float o = red[tid] + red[tid + 64] + red[tid + 128] + red[tid + 192];
        ctxs[b * D + off + tid] = o * inv;
    }
}

// ---------------------------------------------------------------------------
// relu + LayerNorm (+ optional bf16 split outputs)
// ---------------------------------------------------------------------------
__global__ void relu_ln(const float* __restrict__ x, const float* __restrict__ w,
                        const float* __restrict__ bb, float* __restrict__ out,
                        __nv_bfloat16* __restrict__ hi, __nv_bfloat16* __restrict__ lo) {
    __shared__ float red[256];
    int row = blockIdx.x;
    int tid = threadIdx.x;
    float v0 = fmaxf(x[row * D + tid],       0.f);
    float v1 = fmaxf(x[row * D + tid + 256], 0.f);
    red[tid] = v0 + v1;
    __syncthreads();
    for (int st = 128; st > 0; st >>= 1) {
        if (tid < st) red[tid] += red[tid + st];
        __syncthreads();
    }
    float mean = red[0] * (1.f / 512.f);
    __syncthreads();
    float d0 = v0 - mean, d1 = v1 - mean;
    red[tid] = d0 * d0 + d1 * d1;
    __syncthreads();
    for (int st = 128; st > 0; st >>= 1) {
        if (tid < st) red[tid] += red[tid + st];
        __syncthreads();
    }
    float inv = rsqrtf(red[0] * (1.f / 512.f) + 1e-12f);
    float o0 = w[tid]       * d0 * inv + bb[tid];
    float o1 = w[tid + 256] * d1 * inv + bb[tid + 256];
    out[row * D + tid]       = o0;
    out[row * D + tid + 256] = o1;
    if (hi) {
        __nv_bfloat16 h0 = __float2bfloat16_rn(o0);
        __nv_bfloat16 h1 = __float2bfloat16_rn(o1);
        hi[row * D + tid]       = h0;
        hi[row * D + tid + 256] = h1;
        lo[row * D + tid]       = __float2bfloat16_rn(o0 - __bfloat162float(h0));
        lo[row * D + tid + 256] = __float2bfloat16_rn(o1 - __bfloat162float(h1));
    }
}

// ---------------------------------------------------------------------------
// logits = h @ ofc_w[512,17] + ofc_b
// ---------------------------------------------------------------------------
__global__ void final_logits(const float* __restrict__ h, const float* __restrict__ W,
                             const float* __restrict__ bias, float* __restrict__ out) {
    __shared__ float Wsh[512 * T];
    int tid = threadIdx.x;
    for (int i = tid; i < 512 * T; i += 256) Wsh[i] = W[i];
    __syncthreads();
    int warp = tid >> 5, lane = tid & 31;
    int row = blockIdx.x * 8 + warp;
    float acc[T];
    #pragma unroll
    for (int t = 0; t < T; t++) acc[t] = 0.f;
    const float* hr = h + row * D;
    for (int k = lane; k < D; k += 32) {
        float a = hr[k];
        #pragma unroll
        for (int t = 0; t < T; t++) acc[t] = fmaf(a, Wsh[k * T + t], acc[t]);
    }
    #pragma unroll
    for (int t = 0; t < T; t++)
        #pragma unroll
        for (int o = 16; o > 0; o >>= 1)
            acc[t] += __shfl_xor_sync(0xffffffffu, acc[t], o);
    if (lane == 0) {
        #pragma unroll
        for (int t = 0; t < T; t++) out[row * T + t] = acc[t] + bias[t];
    }
}

// ---------------------------------------------------------------------------
// Launch
// ---------------------------------------------------------------------------
extern "C" void kernel_launch(void* const* d_in, const int* in_sizes, int n_in,
                              void* d_out, int out_size) {
    (void)in_sizes; (void)n_in; (void)out_size;
    const int*   tokens  = (const int*)  d_in[0];
    const float* emb     = (const float*)d_in[4];
    Ptr8 wsrc = {{ (const float*)d_in[5],  (const float*)d_in[7],
                   (const float*)d_in[9],  (const float*)d_in[11],
                   (const float*)d_in[13], (const float*)d_in[15],
                   (const float*)d_in[17], (const float*)d_in[19] }};
    Ptr8 bsrc = {{ (const float*)d_in[6],  (const float*)d_in[8],
                   (const float*)d_in[10], (const float*)d_in[12],
                   (const float*)d_in[14], (const float*)d_in[16],
                   (const float*)d_in[18], (const float*)d_in[20] }};
    const float* sat_kw = (const float*)d_in[7];
    const float* sat_kb = (const float*)d_in[8];
    const float* sat_vw = (const float*)d_in[9];
    const float* sat_vb = (const float*)d_in[10];
    const float* rel_qw = (const float*)d_in[13];
    const float* rel_qb = (const float*)d_in[14];
    const float* rel_kw = (const float*)d_in[15];
    const float* rel_kb = (const float*)d_in[16];
    const float* rel_vw = (const float*)d_in[17];
    const float* rel_vb = (const float*)d_in[18];
    const float* rel_ow = (const float*)d_in[19];
    const float* rel_ob = (const float*)d_in[20];
    const float* ln_sw  = (const float*)d_in[21];
    const float* ln_sb  = (const float*)d_in[22];
    const float* ln_rw  = (const float*)d_in[23];
    const float* ln_rb  = (const float*)d_in[24];
    const float* ofc_w  = (const float*)d_in[25];
    const float* ofc_b  = (const float*)d_in[26];
    float* out = (float*)d_out;

    float *e, *h, *s, *qkv, *qkeve, *krvr, *a;
    float *ks, *vs, *qsr, *ksr, *vsr, *ctxs, *r, *bias, *part;
    __nv_bfloat16 *ehi, *elo, *hhi, *hlo, *cthi, *ctlo, *whi, *wlo;
    cudaGetSymbolAddress((void**)&e,     g_e);
    cudaGetSymbolAddress((void**)&h,     g_h);
    cudaGetSymbolAddress((void**)&s,     g_s);
    cudaGetSymbolAddress((void**)&qkv,   g_qkv);
    cudaGetSymbolAddress((void**)&qkeve, g_qkeve);
    cudaGetSymbolAddress((void**)&krvr,  g_krvr);
    cudaGetSymbolAddress((void**)&a,     g_a);
    cudaGetSymbolAddress((void**)&ks,    g_ks);
    cudaGetSymbolAddress((void**)&vs,    g_vs);
    cudaGetSymbolAddress((void**)&qsr,   g_qsr);
    cudaGetSymbolAddress((void**)&ksr,   g_ksr);
    cudaGetSymbolAddress((void**)&vsr,   g_vsr);
    cudaGetSymbolAddress((void**)&ctxs,  g_ctxs);
    cudaGetSymbolAddress((void**)&r,     g_r);
    cudaGetSymbolAddress((void**)&bias,  g_bias);
    cudaGetSymbolAddress((void**)&part,  g_part);
    cudaGetSymbolAddress((void**)&ehi,   g_ehi);
    cudaGetSymbolAddress((void**)&elo,   g_elo);
    cudaGetSymbolAddress((void**)&hhi,   g_hhi);
    cudaGetSymbolAddress((void**)&hlo,   g_hlo);
    cudaGetSymbolAddress((void**)&cthi,  g_cthi);
    cudaGetSymbolAddress((void**)&ctlo,  g_ctlo);
    cudaGetSymbolAddress((void**)&whi,   g_whi);
    cudaGetSymbolAddress((void**)&wlo,   g_wlo);

    cudaFuncSetAttribute(mma_gemm, cudaFuncAttributeMaxDynamicSharedMemorySize,
                         SMEM_BYTES);

    #define GEMM(AHI, ALO, WI, NTOT, OUT, LDC)                                 \
        mma_gemm<<<dim3((NTOT) / 128, 64), 256, SMEM_BYTES>>>(                 \
            AHI, ALO, whi + (WI) * DD, wlo + (WI) * DD, bias + (WI) * 512,     \
            OUT, LDC)

    #define SMALL(AIN, JOBS, NJ)                                               \
        do {                                                                   \
            sgemm16_part<<<dim3(8, NJ), 256>>>(AIN, JOBS, part);               \
            sgemm16_red<<<dim3(32, NJ), 256>>>(JOBS, part);                    \
        } while (0)

    // Weight prep
    wsplit_all<<<dim3(16, 16, 8), dim3(32, 8)>>>(wsrc, whi, wlo);
    biascat<<<16, 256>>>(bsrc, bias);

    embed_split<<<BL * D / 256, 256>>>(tokens, emb, e, ehi, elo);

    // Cycle-0 fused projection from e: q | ke | ve (weights 0,1,2 contiguous).
    // First GEMM launch → also the one ncu captures.
    GEMM(ehi, elo, 0, 1536, qkeve, 1536);

    smean_kernel<<<B * 8, 256>>>(e, s);

    for (int c = 0; c < CYC; c++) {
        const bool last = (c == CYC - 1);

        {
            SJobs j = {{ sat_kw, sat_vw, nullptr },
                       { sat_kb, sat_vb, nullptr },
                       { ks, vs, nullptr }};
            SMALL(s, j, 2);
        }

        if (c == 0) {
            // h == e: K(h)=ke, V(h)=ve — all in qkeve.
            sat_attn<<<BL, 256>>>(qkeve, 1536,
                                  qkeve + 512, qkeve + 1024, 1536,
                                  qkeve + 512, qkeve + 1024, 1536,
                                  ks, vs, cthi, ctlo);
        } else {
            GEMM(hhi, hlo, 0, 1536, qkv, 1536);   // q | k | v
            sat_attn<<<BL, 256>>>(qkv, 1536,
                                  qkv + 512, qkv + 1024, 1536,
                                  qkeve + 512, qkeve + 1024, 1536,
                                  ks, vs, cthi, ctlo);
        }

        GEMM(cthi, ctlo, 3, 512, a, 512);         // sat_o
        relu_ln<<<BL, 256>>>(a, ln_sw, ln_sb, h,
                             last ? nullptr : hhi, last ? nullptr : hlo);

        // rel path is dead on the final cycle (s never consumed again)
        if (!last) {
            GEMM(hhi, hlo, 5, 1024, krvr, 1024);  // rel_k | rel_v
            {
                SJobs j = {{ rel_qw, rel_kw, rel_vw },
                           { rel_qb, rel_kb, rel_vb },
                           { qsr, ksr, vsr }};
                SMALL(s, j, 3);
            }

            rel_attn<<<B * NH, 256>>>(qsr, ksr, krvr, vsr, ctxs);
            {
                SJobs j = {{ rel_ow, nullptr, nullptr },
                           { rel_ob, nullptr, nullptr },
                           { r, nullptr, nullptr }};
                SMALL(ctxs, j, 1);
            }
            relu_ln<<<B, 256>>>(r, ln_rw, ln_rb, s, nullptr, nullptr);
        }
    }

    final_logits<<<BL / 8, 256>>>(h, ofc_w, ofc_b, out);
}